// round 6
// baseline (speedup 1.0000x reference)
#include <cuda_runtime.h>

// ---------------------------------------------------------------------------
// Static scratch (no allocation allowed)
// ---------------------------------------------------------------------------
__device__ float g_bufA[16777216];
__device__ float g_bufB[4194304];
__device__ float g_Wp[279936];      // [k1lin 27][k2lin 27][ci 128][co 3]
__device__ float g_Weff[110592];    // [pz 8][dxlin 27][ci 128][4] (co + pad)
__device__ float g_bconv[81];       // [k2lin 27][co 3]
__device__ float g_btot[3];

typedef unsigned long long ull;

// ---------------------------------------------------------------------------
// f32x2 packed helpers
// ---------------------------------------------------------------------------
__device__ __forceinline__ ull pack2(float x, float y){
  ull r; asm("mov.b64 %0, {%1, %2};" : "=l"(r) : "f"(x), "f"(y)); return r;
}
__device__ __forceinline__ void unpack2(ull v, float& x, float& y){
  asm("mov.b64 {%0, %1}, %2;" : "=f"(x), "=f"(y) : "l"(v));
}
__device__ __forceinline__ void ffma2(ull& acc, ull a, ull b){
  asm("fma.rn.f32x2 %0, %1, %2, %0;" : "+l"(acc) : "l"(a), "l"(b));
}

// ---------------------------------------------------------------------------
// ROUND-1 PROVEN KERNEL (verbatim): generic transposed-conv implicit GEMM.
// ---------------------------------------------------------------------------
template<int BM, int TM>
__global__ __launch_bounds__(256) void deconv_gemm(
    const float* __restrict__ x, const float* __restrict__ w,
    const float* __restrict__ bias, float* __restrict__ out,
    int inD, int inH, int inW, int Cin,
    int outD, int outH, int outW, int Cout,
    int stride, int relu)
{
  constexpr int BN = 64;
  constexpr int BK = 16;
  constexpr int NP = TM / 2;

  __shared__ float As[BK][BM];
  __shared__ float Bs[BK][BN];
  __shared__ int   offs[BM];

  const int tid = threadIdx.x;
  const int pz = blockIdx.z;
  const int pd = (pz >> 2) & 1, ph = (pz >> 1) & 1, pw = pz & 1;
  const int rH = outH / stride, rW = outW / stride;
  const int nb = blockIdx.y * BN;
  const int vbase = blockIdx.x * BM;

  int md = 0, mh = 0, mw = 0;
  if (tid < BM) {
    int rv = vbase + tid;
    mw = rv % rW; int t = rv / rW; mh = t % rH; md = t / rH;
  }

  int nkd, kdL[3], ddL[3];
  int nkh, khL[3], dhL[3];
  int nkw, kwL[3], dwL[3];
  auto mk = [&](int p, int& n, int* kL, int* dL){
    if (stride == 1){ n = 3; kL[0]=0; kL[1]=1; kL[2]=2; dL[0]=-1; dL[1]=0; dL[2]=1; }
    else if (p == 0){ n = 2; kL[0]=0; kL[1]=2; dL[0]=-1; dL[1]=0; }
    else            { n = 1; kL[0]=1; dL[0]=0; }
  };
  mk(pd, nkd, kdL, ddL);
  mk(ph, nkh, khL, dhL);
  mk(pw, nkw, kwL, dwL);

  const int mg = tid >> 4, ng = tid & 15;
  const int m0 = mg * TM, n0 = ng * 4;

  ull acc[NP][4];
  #pragma unroll
  for (int i = 0; i < NP; i++)
    #pragma unroll
    for (int j = 0; j < 4; j++) acc[i][j] = 0ull;

  for (int ia = 0; ia < nkd; ia++)
  for (int ib = 0; ib < nkh; ib++)
  for (int ic = 0; ic < nkw; ic++){
    const int tap = (kdL[ia]*3 + khL[ib])*3 + kwL[ic];
    const float* wt = w + (size_t)tap * Cin * Cout + nb;

    __syncthreads();
    if (tid < BM){
      int id = md + ddL[ia];
      int ih = mh + dhL[ib];
      int iw = mw + dwL[ic];
      bool v = (unsigned)id < (unsigned)inD &&
               (unsigned)ih < (unsigned)inH &&
               (unsigned)iw < (unsigned)inW;
      offs[tid] = v ? ((id*inH + ih)*inW + iw) * Cin : -1;
    }

    for (int c0 = 0; c0 < Cin; c0 += BK){
      __syncthreads();
      for (int idx = tid; idx < BM*4; idx += 256){
        int v = idx >> 2, c4 = (idx & 3) * 4;
        int o = offs[v];
        float4 val = make_float4(0.f, 0.f, 0.f, 0.f);
        if (o >= 0) val = *(const float4*)(x + o + c0 + c4);
        As[c4+0][v] = val.x; As[c4+1][v] = val.y;
        As[c4+2][v] = val.z; As[c4+3][v] = val.w;
      }
      {
        int r = tid >> 4, col = (tid & 15) * 4;
        float4 bv = *(const float4*)(wt + (size_t)(c0 + r) * Cout + col);
        *(float4*)&Bs[r][col] = bv;
      }
      __syncthreads();
      #pragma unroll
      for (int kk = 0; kk < BK; kk++){
        const ull* a64 = (const ull*)&As[kk][m0];
        float4 bv = *(const float4*)&Bs[kk][n0];
        ull bp0 = pack2(bv.x, bv.x);
        ull bp1 = pack2(bv.y, bv.y);
        ull bp2 = pack2(bv.z, bv.z);
        ull bp3 = pack2(bv.w, bv.w);
        #pragma unroll
        for (int i = 0; i < NP; i++){
          ull av = a64[i];
          ffma2(acc[i][0], av, bp0);
          ffma2(acc[i][1], av, bp1);
          ffma2(acc[i][2], av, bp2);
          ffma2(acc[i][3], av, bp3);
        }
      }
    }
  }

  float4 b4 = *(const float4*)&bias[nb + n0];
  #pragma unroll
  for (int i = 0; i < NP; i++){
    float r0[4], r1[4];
    #pragma unroll
    for (int j = 0; j < 4; j++) unpack2(acc[i][j], r0[j], r1[j]);
    #pragma unroll
    for (int h = 0; h < 2; h++){
      float* rr = h ? r1 : r0;
      int rv = vbase + m0 + 2*i + h;
      int vw = rv % rW; int t = rv / rW; int vh = t % rH; int vd = t / rH;
      int od = vd*stride + pd, oh = vh*stride + ph, ow = vw*stride + pw;
      size_t oo = (size_t)((od*outH + oh)*outW + ow) * Cout + nb + n0;
      float4 res;
      res.x = rr[0] + b4.x; res.y = rr[1] + b4.y;
      res.z = rr[2] + b4.z; res.w = rr[3] + b4.w;
      if (relu){
        res.x = fmaxf(res.x, 0.f); res.y = fmaxf(res.y, 0.f);
        res.z = fmaxf(res.z, 0.f); res.w = fmaxf(res.w, 0.f);
      }
      *(float4*)&out[oo] = res;
    }
  }
}

// ---------------------------------------------------------------------------
// ROUND-3 PROVEN KERNEL (verbatim): stride-1 C=128 + ReLU (L4).
// ---------------------------------------------------------------------------
template<int DIM>
__global__ __launch_bounds__(256) void deconv_s1r(
    const float* __restrict__ x, const float* __restrict__ w,
    const float* __restrict__ bias, float* __restrict__ out)
{
  constexpr int C  = 128;
  constexpr int BM = 128;
  constexpr int BK = 16;

  __shared__ float As[BK][BM];
  __shared__ float Bs[BK][C];
  __shared__ int   offs[BM];

  const int tid = threadIdx.x;
  const int vbase = blockIdx.x * BM;
  const int mg = tid >> 4;
  const int ng = tid & 15;
  const int m0 = mg * 8;

  int md, mh, mw;
  {
    int rv = vbase + (tid & (BM-1));
    mw = rv & (DIM-1); int t = rv / DIM; mh = t & (DIM-1); md = t / DIM;
  }

  ull acc[4][8];
  #pragma unroll
  for (int i = 0; i < 4; i++)
    #pragma unroll
    for (int j = 0; j < 8; j++) acc[i][j] = 0ull;

  for (int tap = 0; tap < 27; tap++){
    const int kw = tap % 3, kh = (tap / 3) % 3, kd = tap / 9;
    const float* wt = w + tap * C * C;

    __syncthreads();
    if (tid < BM){
      int id = md + kd - 1, ih = mh + kh - 1, iw = mw + kw - 1;
      bool v = (unsigned)id < (unsigned)DIM &&
               (unsigned)ih < (unsigned)DIM &&
               (unsigned)iw < (unsigned)DIM;
      offs[tid] = v ? ((id*DIM + ih)*DIM + iw) * C : -1;
    }

    for (int c0 = 0; c0 < C; c0 += BK){
      __syncthreads();
      #pragma unroll
      for (int idx = tid; idx < BM*4; idx += 256){
        int v = idx >> 2, q = idx & 3;
        int o = offs[v];
        float4 val = make_float4(0.f, 0.f, 0.f, 0.f);
        if (o >= 0) val = *(const float4*)(x + o + c0 + q*4);
        As[q*4+0][v] = val.x; As[q*4+1][v] = val.y;
        As[q*4+2][v] = val.z; As[q*4+3][v] = val.w;
      }
      #pragma unroll
      for (int idx = tid; idx < BK*(C/4); idx += 256){
        int r = idx >> 5, c4 = (idx & 31) * 4;
        *(float4*)&Bs[r][c4] = *(const float4*)(wt + (c0 + r)*C + c4);
      }
      __syncthreads();
      #pragma unroll
      for (int kk = 0; kk < BK; kk++){
        float4 a0 = *(const float4*)&As[kk][m0];
        float4 a1 = *(const float4*)&As[kk][m0 + 4];
        ull av[4];
        av[0] = pack2(a0.x, a0.y); av[1] = pack2(a0.z, a0.w);
        av[2] = pack2(a1.x, a1.y); av[3] = pack2(a1.z, a1.w);
        #pragma unroll
        for (int j = 0; j < 4; j++){
          float2 bv = *(const float2*)&Bs[kk][2*(ng + j*16)];
          ull b0 = pack2(bv.x, bv.x);
          ull b1 = pack2(bv.y, bv.y);
          #pragma unroll
          for (int i = 0; i < 4; i++){
            ffma2(acc[i][2*j+0], av[i], b0);
            ffma2(acc[i][2*j+1], av[i], b1);
          }
        }
      }
    }
  }

  float2 bb[4];
  #pragma unroll
  for (int j = 0; j < 4; j++)
    bb[j] = *(const float2*)&bias[2*(ng + j*16)];

  #pragma unroll
  for (int i = 0; i < 4; i++){
    float v0[8], v1[8];
    #pragma unroll
    for (int t = 0; t < 8; t++) unpack2(acc[i][t], v0[t], v1[t]);
    #pragma unroll
    for (int h = 0; h < 2; h++){
      float* vv = h ? v1 : v0;
      size_t oo = (size_t)(vbase + m0 + 2*i + h) * C;
      #pragma unroll
      for (int j = 0; j < 4; j++){
        float2 r;
        r.x = fmaxf(vv[2*j+0] + bb[j].x, 0.f);
        r.y = fmaxf(vv[2*j+1] + bb[j].y, 0.f);
        *(float2*)&out[oo + 2*(ng + j*16)] = r;
      }
    }
  }
}

// ---------------------------------------------------------------------------
// Fused L5+L6 path tables: per (parity p, dx+1): list of (k1, k2) per dim.
// Derived from: y[2r]<-x[r-1](k1=0),x[r](k1=2); y[2r+1]<-x[r](k1=1);
//               z[o] = sum_k2 w20[k2]*y[o+k2-1].
// ---------------------------------------------------------------------------
__device__ __constant__ int c_np[2][3]   = {{2,2,0},{1,3,1}};
__device__ __constant__ int c_k1[2][3][3] = {{{1,0,0},{2,1,0},{0,0,0}},
                                             {{0,0,0},{2,1,0},{2,0,0}}};
__device__ __constant__ int c_k2[2][3][3] = {{{0,1,0},{1,2,0},{0,0,0}},
                                             {{0,0,0},{0,1,2},{2,0,0}}};

// P1: Wp[k1][k2][ci][co] = sum_cm w2[k1,ci,cm] * w20[k2,cm,co]
__global__ __launch_bounds__(256) void p1_wp(
    const float* __restrict__ w2, const float* __restrict__ w20)
{
  int t = blockIdx.x * 256 + threadIdx.x;
  if (t >= 27*27*128) return;
  int ci = t & 127;
  int k2l = (t >> 7) % 27;
  int k1l = t / (27*128);
  const float* a = w2 + ((size_t)k1l*128 + ci) * 64;
  const float* b = w20 + (size_t)k2l * 64 * 3;
  float s0 = 0.f, s1 = 0.f, s2 = 0.f;
  #pragma unroll 4
  for (int cm = 0; cm < 64; cm++){
    float av = a[cm];
    s0 = fmaf(av, b[cm*3+0], s0);
    s1 = fmaf(av, b[cm*3+1], s1);
    s2 = fmaf(av, b[cm*3+2], s2);
  }
  float* o = g_Wp + (size_t)t * 3;
  o[0] = s0; o[1] = s1; o[2] = s2;
}

// P2: Weff[pz][dxlin][ci][{co,pad}] = sum over per-dim path combos of Wp
__global__ __launch_bounds__(256) void p2_weff()
{
  int t = blockIdx.x * 256 + threadIdx.x;
  if (t >= 8*27*128) return;
  int ci = t & 127;
  int dxl = (t >> 7) % 27;
  int pz = t / (27*128);
  int jd = dxl / 9, jh = (dxl / 3) % 3, jw = dxl % 3;   // dx+1 per dim
  int pd = (pz >> 2) & 1, ph = (pz >> 1) & 1, pw = pz & 1;
  int nd = c_np[pd][jd], nh = c_np[ph][jh], nw = c_np[pw][jw];
  float s0 = 0.f, s1 = 0.f, s2 = 0.f;
  for (int a = 0; a < nd; a++)
  for (int b = 0; b < nh; b++)
  for (int c = 0; c < nw; c++){
    int k1l = (c_k1[pd][jd][a]*3 + c_k1[ph][jh][b])*3 + c_k1[pw][jw][c];
    int k2l = (c_k2[pd][jd][a]*3 + c_k2[ph][jh][b])*3 + c_k2[pw][jw][c];
    const float* wp = g_Wp + ((size_t)(k1l*27 + k2l)*128 + ci)*3;
    s0 += wp[0]; s1 += wp[1]; s2 += wp[2];
  }
  float* o = g_Weff + (size_t)t * 4;
  o[0] = s0; o[1] = s1; o[2] = s2; o[3] = 0.f;
}

// P3: bconv[k2][co] = sum_cm w20[k2,cm,co]*b2[cm];  btot = b20 + sum_k2 bconv
__global__ void p3_bias(const float* __restrict__ w20,
                        const float* __restrict__ b2,
                        const float* __restrict__ b20)
{
  int tid = threadIdx.x;
  if (tid < 81){
    int k2 = tid / 3, co = tid % 3;
    float s = 0.f;
    for (int cm = 0; cm < 64; cm++)
      s = fmaf(w20[(k2*64+cm)*3+co], b2[cm], s);
    g_bconv[tid] = s;
  }
  __syncthreads();
  if (tid < 3){
    float s = b20[tid];
    for (int k2 = 0; k2 < 27; k2++) s += g_bconv[k2*3+tid];
    g_btot[tid] = s;
  }
}

// ---------------------------------------------------------------------------
// Fused L5+L6 main kernel: x(32^3,128) -> out(64^3,3), no activation.
// CTA: 512 reduced-grid voxels (one parity class), 256 threads = 8 k-octant
// warps x 32 voxel-groups (16 voxels each). Weights read from gmem (uniform
// broadcast, L1-hot). Accumulators: 8 voxel-pairs x 3 couts as f32x2.
// Cross-octant reduction via SMEM at the end. Boundary planes (o=0/63) are
// written with collapsed weights here and OVERWRITTEN exactly by fix56.
// ---------------------------------------------------------------------------
__global__ __launch_bounds__(256) void fused56(
    const float* __restrict__ x, float* __restrict__ out)
{
  extern __shared__ char dyn[];
  float (*As)[512] = (float(*)[512])dyn;            // [16][512] = 32KB
  ull*  RED  = (ull*)dyn;                           // [768][8]  = 48KB (after)
  int*  offs = (int*)(dyn + 49152);                 // 512 ints

  const int tid  = threadIdx.x;
  const int oct  = tid >> 5;
  const int lane = tid & 31;
  const int m0   = lane * 16;
  const int pz = blockIdx.z;
  const int pd = (pz >> 2) & 1, ph = (pz >> 1) & 1, pw = pz & 1;
  const int vbase = blockIdx.x * 512;
  const int nd = 2 + pd, nh = 2 + ph, nw = 2 + pw;

  ull acc[8][3];
  #pragma unroll
  for (int p = 0; p < 8; p++)
    #pragma unroll
    for (int c = 0; c < 3; c++) acc[p][c] = 0ull;

  for (int jd = 0; jd < nd; jd++)
  for (int jh = 0; jh < nh; jh++)
  for (int jw = 0; jw < nw; jw++){
    const int dd = jd - 1, dh = jh - 1, dw = jw - 1;
    const int dxl = jd*9 + jh*3 + jw;
    const float4* Wg = (const float4*)g_Weff + (pz*27 + dxl)*128;

    __syncthreads();                // prior As/offs readers done
    for (int v = tid; v < 512; v += 256){
      int q = vbase + v;
      int qw_ = q & 31, qh_ = (q >> 5) & 31, qd_ = q >> 10;
      int id = qd_ + dd, ih = qh_ + dh, iw = qw_ + dw;
      bool ok = (unsigned)id < 32u && (unsigned)ih < 32u && (unsigned)iw < 32u;
      offs[v] = ok ? ((id*32 + ih)*32 + iw) * 128 : -1;
    }

    for (int c0 = 0; c0 < 128; c0 += 16){
      __syncthreads();
      #pragma unroll
      for (int idx = tid; idx < 2048; idx += 256){
        int v = idx >> 2, q4 = (idx & 3) * 4;
        int o = offs[v];
        float4 val = make_float4(0.f, 0.f, 0.f, 0.f);
        if (o >= 0) val = *(const float4*)(x + o + c0 + q4);
        As[q4+0][v] = val.x; As[q4+1][v] = val.y;
        As[q4+2][v] = val.z; As[q4+3][v] = val.w;
      }
      __syncthreads();
      #pragma unroll
      for (int kx = 0; kx < 2; kx++){
        const int kk = 2*oct + kx;
        float4 wv = __ldg(&Wg[c0 + kk]);
        ull b0 = pack2(wv.x, wv.x);
        ull b1 = pack2(wv.y, wv.y);
        ull b2 = pack2(wv.z, wv.z);
        const ull* a64 = (const ull*)&As[kk][m0];
        #pragma unroll
        for (int p = 0; p < 8; p++){
          ull av = a64[p];
          ffma2(acc[p][0], av, b0);
          ffma2(acc[p][1], av, b1);
          ffma2(acc[p][2], av, b2);
        }
      }
    }
  }

  // cross-octant reduction
  __syncthreads();
  #pragma unroll
  for (int p = 0; p < 8; p++)
    #pragma unroll
    for (int c = 0; c < 3; c++)
      RED[((lane*8 + p)*3 + c)*8 + oct] = acc[p][c];
  __syncthreads();

  for (int e = tid; e < 768; e += 256){
    const ull* r = &RED[e*8];
    float s0 = 0.f, s1 = 0.f;
    #pragma unroll
    for (int o = 0; o < 8; o++){
      float a, b; unpack2(r[o], a, b);
      s0 += a; s1 += b;
    }
    int pairIdx = e / 3, co = e % 3;
    float bias = __ldg(&g_btot[co]);
    #pragma unroll
    for (int h = 0; h < 2; h++){
      int v = 2*pairIdx + h;
      int q = vbase + v;
      int qw_ = q & 31, qh_ = (q >> 5) & 31, qd_ = q >> 10;
      int od = 2*qd_ + pd, oh = 2*qh_ + ph, ow = 2*qw_ + pw;
      out[((od*64 + oh)*64 + ow)*3 + co] = (h ? s1 : s0) + bias;
    }
  }
}

// ---------------------------------------------------------------------------
// fix56: exact recompute of the 6 boundary planes (any o-dim in {0,63}).
// Uses Wp with explicit (k2 validity, k1/ix validity) path sums + exact bias.
// ---------------------------------------------------------------------------
__global__ __launch_bounds__(256) void fix56(
    const float* __restrict__ x, const float* __restrict__ b20,
    float* __restrict__ out)
{
  int idx = blockIdx.x * 256 + threadIdx.x;
  if (idx >= 6*4096) return;
  int plane = idx / 4096, r = idx % 4096;
  int a = r / 64, b = r % 64;
  int od, oh, ow;
  if      (plane == 0){ od = 0;  oh = a; ow = b; }
  else if (plane == 1){ od = 63; oh = a; ow = b; }
  else if (plane == 2){ oh = 0;  od = a; ow = b; if (od==0||od==63) return; }
  else if (plane == 3){ oh = 63; od = a; ow = b; if (od==0||od==63) return; }
  else if (plane == 4){ ow = 0;  od = a; oh = b; if (od==0||od==63||oh==0||oh==63) return; }
  else               { ow = 63; od = a; oh = b; if (od==0||od==63||oh==0||oh==63) return; }

  float acc0 = __ldg(&b20[0]), acc1 = __ldg(&b20[1]), acc2 = __ldg(&b20[2]);

  for (int k2d = 0; k2d < 3; k2d++){
    int md = od + k2d - 1; if ((unsigned)md >= 64u) continue;
    int pmd = md & 1, rd = (md - pmd) >> 1;
    int n_d = pmd ? 1 : 2;
    int k1d[2], ixd[2];
    if (pmd){ k1d[0] = 1; ixd[0] = rd; }
    else    { k1d[0] = 0; ixd[0] = rd - 1; k1d[1] = 2; ixd[1] = rd; }
    for (int k2h = 0; k2h < 3; k2h++){
      int mh = oh + k2h - 1; if ((unsigned)mh >= 64u) continue;
      int pmh = mh & 1, rh = (mh - pmh) >> 1;
      int n_h = pmh ? 1 : 2;
      int k1h[2], ixh[2];
      if (pmh){ k1h[0] = 1; ixh[0] = rh; }
      else    { k1h[0] = 0; ixh[0] = rh - 1; k1h[1] = 2; ixh[1] = rh; }
      for (int k2w = 0; k2w < 3; k2w++){
        int mw = ow + k2w - 1; if ((unsigned)mw >= 64u) continue;
        int pmw = mw & 1, rw = (mw - pmw) >> 1;
        int n_w = pmw ? 1 : 2;
        int k1w[2], ixw[2];
        if (pmw){ k1w[0] = 1; ixw[0] = rw; }
        else    { k1w[0] = 0; ixw[0] = rw - 1; k1w[1] = 2; ixw[1] = rw; }

        int k2l = (k2d*3 + k2h)*3 + k2w;
        acc0 += g_bconv[k2l*3+0];
        acc1 += g_bconv[k2l*3+1];
        acc2 += g_bconv[k2l*3+2];

        for (int ia = 0; ia < n_d; ia++){
          if ((unsigned)ixd[ia] >= 32u) continue;
          for (int ib = 0; ib < n_h; ib++){
            if ((unsigned)ixh[ib] >= 32u) continue;
            for (int ic = 0; ic < n_w; ic++){
              if ((unsigned)ixw[ic] >= 32u) continue;
              int k1l = (k1d[ia]*3 + k1h[ib])*3 + k1w[ic];
              const float* wp = g_Wp + (size_t)(k1l*27 + k2l)*384;
              const float* xp = x + (size_t)((ixd[ia]*32 + ixh[ib])*32 + ixw[ic])*128;
              #pragma unroll 4
              for (int c4 = 0; c4 < 32; c4++){
                float4 xv = *(const float4*)(xp + c4*4);
                const float* w4 = wp + c4*12;
                acc0 = fmaf(xv.x, w4[0],  acc0);
                acc1 = fmaf(xv.x, w4[1],  acc1);
                acc2 = fmaf(xv.x, w4[2],  acc2);
                acc0 = fmaf(xv.y, w4[3],  acc0);
                acc1 = fmaf(xv.y, w4[4],  acc1);
                acc2 = fmaf(xv.y, w4[5],  acc2);
                acc0 = fmaf(xv.z, w4[6],  acc0);
                acc1 = fmaf(xv.z, w4[7],  acc1);
                acc2 = fmaf(xv.z, w4[8],  acc2);
                acc0 = fmaf(xv.w, w4[9],  acc0);
                acc1 = fmaf(xv.w, w4[10], acc1);
                acc2 = fmaf(xv.w, w4[11], acc2);
              }
            }
          }
        }
      }
    }
  }

  float* op = out + (size_t)((od*64 + oh)*64 + ow) * 3;
  op[0] = acc0; op[1] = acc1; op[2] = acc2;
}

// ---------------------------------------------------------------------------
// kernel_launch
// ---------------------------------------------------------------------------
extern "C" void kernel_launch(void* const* d_in, const int* in_sizes, int n_in,
                              void* d_out, int out_size)
{
  (void)in_sizes; (void)n_in; (void)out_size;
  const float* x   = (const float*)d_in[0];
  const float* w0  = (const float*)d_in[1];
  const float* b0  = (const float*)d_in[2];
  const float* w00 = (const float*)d_in[3];
  const float* b00 = (const float*)d_in[4];
  const float* w1  = (const float*)d_in[5];
  const float* b1  = (const float*)d_in[6];
  const float* w10 = (const float*)d_in[7];
  const float* b10 = (const float*)d_in[8];
  const float* w2  = (const float*)d_in[9];
  const float* b2  = (const float*)d_in[10];
  const float* w20 = (const float*)d_in[11];
  const float* b20 = (const float*)d_in[12];
  float* out = (float*)d_out;

  float *bufA = nullptr, *bufB = nullptr;
  cudaGetSymbolAddress((void**)&bufA, g_bufA);
  cudaGetSymbolAddress((void**)&bufB, g_bufB);

  // Precompute fused L5+L6 weights (depends only on inputs w2,w20,b2,b20)
  p1_wp<<<(27*27*128 + 255)/256, 256>>>(w2, w20);
  p2_weff<<<(8*27*128 + 255)/256, 256>>>();
  p3_bias<<<1, 128>>>(w20, b2, b20);

  // L1: deconv0 s2: x(8^3,128) -> bufA(16^3,128)   [R1 proven]
  {
    dim3 g(512/32, 128/64, 8);
    deconv_gemm<32,2><<<g, 256>>>(x,  w0,  b0,  bufA,
                                  8,8,8,128,  16,16,16,128, 2, 0);
  }
  // L2: deconv0_0 s1 + relu: bufA -> bufB(16^3,128)   [R1 proven]
  {
    dim3 g(4096/32, 128/64, 1);
    deconv_gemm<32,2><<<g, 256>>>(bufA, w00, b00, bufB,
                                  16,16,16,128, 16,16,16,128, 1, 1);
  }
  // L3: deconv1 s2: bufB -> bufA(32^3,128)   [R1 proven]
  {
    dim3 g(4096/128, 128/64, 8);
    deconv_gemm<128,8><<<g, 256>>>(bufB, w1, b1, bufA,
                                   16,16,16,128, 32,32,32,128, 2, 0);
  }
  // L4: deconv1_0 s1 + relu: bufA -> bufB(32^3,128)   [R3 proven]
  deconv_s1r<32><<<32768/128, 256>>>(bufA, w10, b10, bufB);

  // Fused L5+L6: bufB(32^3,128) -> out(64^3,3)
  {
    const int smem = 49152 + 2048;
    cudaFuncSetAttribute(fused56,
                         cudaFuncAttributeMaxDynamicSharedMemorySize, smem);
    dim3 g(64, 1, 8);
    fused56<<<g, 256, smem>>>(bufB, out);
  }
  // Exact boundary fix (o=0/63 planes)
  fix56<<<96, 256>>>(bufB, b20, out);
}

// round 7
// speedup vs baseline: 1.3937x; 1.3937x over previous
#include <cuda_runtime.h>

// ---------------------------------------------------------------------------
// Static scratch (no allocation allowed)
// ---------------------------------------------------------------------------
__device__ float g_bufA[16777216];
__device__ float g_bufB[4194304];
__device__ float g_Wp[279936];      // [k1lin 27][k2lin 27][ci 128][co 3]
__device__ float g_Weff[110592];    // [pz 8][dxlin 27][co 3][ci 128]  (ci-major)
__device__ float g_bconv[81];       // [k2lin 27][co 3]
__device__ float g_btot[3];

typedef unsigned long long ull;

// ---------------------------------------------------------------------------
// f32x2 packed helpers
// ---------------------------------------------------------------------------
__device__ __forceinline__ ull pack2(float x, float y){
  ull r; asm("mov.b64 %0, {%1, %2};" : "=l"(r) : "f"(x), "f"(y)); return r;
}
__device__ __forceinline__ void unpack2(ull v, float& x, float& y){
  asm("mov.b64 {%0, %1}, %2;" : "=f"(x), "=f"(y) : "l"(v));
}
__device__ __forceinline__ void ffma2(ull& acc, ull a, ull b){
  asm("fma.rn.f32x2 %0, %1, %2, %0;" : "+l"(acc) : "l"(a), "l"(b));
}

// ---------------------------------------------------------------------------
// ROUND-1 PROVEN KERNEL (verbatim): generic transposed-conv implicit GEMM.
// ---------------------------------------------------------------------------
template<int BM, int TM>
__global__ __launch_bounds__(256) void deconv_gemm(
    const float* __restrict__ x, const float* __restrict__ w,
    const float* __restrict__ bias, float* __restrict__ out,
    int inD, int inH, int inW, int Cin,
    int outD, int outH, int outW, int Cout,
    int stride, int relu)
{
  constexpr int BN = 64;
  constexpr int BK = 16;
  constexpr int NP = TM / 2;

  __shared__ float As[BK][BM];
  __shared__ float Bs[BK][BN];
  __shared__ int   offs[BM];

  const int tid = threadIdx.x;
  const int pz = blockIdx.z;
  const int pd = (pz >> 2) & 1, ph = (pz >> 1) & 1, pw = pz & 1;
  const int rH = outH / stride, rW = outW / stride;
  const int nb = blockIdx.y * BN;
  const int vbase = blockIdx.x * BM;

  int md = 0, mh = 0, mw = 0;
  if (tid < BM) {
    int rv = vbase + tid;
    mw = rv % rW; int t = rv / rW; mh = t % rH; md = t / rH;
  }

  int nkd, kdL[3], ddL[3];
  int nkh, khL[3], dhL[3];
  int nkw, kwL[3], dwL[3];
  auto mk = [&](int p, int& n, int* kL, int* dL){
    if (stride == 1){ n = 3; kL[0]=0; kL[1]=1; kL[2]=2; dL[0]=-1; dL[1]=0; dL[2]=1; }
    else if (p == 0){ n = 2; kL[0]=0; kL[1]=2; dL[0]=-1; dL[1]=0; }
    else            { n = 1; kL[0]=1; dL[0]=0; }
  };
  mk(pd, nkd, kdL, ddL);
  mk(ph, nkh, khL, dhL);
  mk(pw, nkw, kwL, dwL);

  const int mg = tid >> 4, ng = tid & 15;
  const int m0 = mg * TM, n0 = ng * 4;

  ull acc[NP][4];
  #pragma unroll
  for (int i = 0; i < NP; i++)
    #pragma unroll
    for (int j = 0; j < 4; j++) acc[i][j] = 0ull;

  for (int ia = 0; ia < nkd; ia++)
  for (int ib = 0; ib < nkh; ib++)
  for (int ic = 0; ic < nkw; ic++){
    const int tap = (kdL[ia]*3 + khL[ib])*3 + kwL[ic];
    const float* wt = w + (size_t)tap * Cin * Cout + nb;

    __syncthreads();
    if (tid < BM){
      int id = md + ddL[ia];
      int ih = mh + dhL[ib];
      int iw = mw + dwL[ic];
      bool v = (unsigned)id < (unsigned)inD &&
               (unsigned)ih < (unsigned)inH &&
               (unsigned)iw < (unsigned)inW;
      offs[tid] = v ? ((id*inH + ih)*inW + iw) * Cin : -1;
    }

    for (int c0 = 0; c0 < Cin; c0 += BK){
      __syncthreads();
      for (int idx = tid; idx < BM*4; idx += 256){
        int v = idx >> 2, c4 = (idx & 3) * 4;
        int o = offs[v];
        float4 val = make_float4(0.f, 0.f, 0.f, 0.f);
        if (o >= 0) val = *(const float4*)(x + o + c0 + c4);
        As[c4+0][v] = val.x; As[c4+1][v] = val.y;
        As[c4+2][v] = val.z; As[c4+3][v] = val.w;
      }
      {
        int r = tid >> 4, col = (tid & 15) * 4;
        float4 bv = *(const float4*)(wt + (size_t)(c0 + r) * Cout + col);
        *(float4*)&Bs[r][col] = bv;
      }
      __syncthreads();
      #pragma unroll
      for (int kk = 0; kk < BK; kk++){
        const ull* a64 = (const ull*)&As[kk][m0];
        float4 bv = *(const float4*)&Bs[kk][n0];
        ull bp0 = pack2(bv.x, bv.x);
        ull bp1 = pack2(bv.y, bv.y);
        ull bp2 = pack2(bv.z, bv.z);
        ull bp3 = pack2(bv.w, bv.w);
        #pragma unroll
        for (int i = 0; i < NP; i++){
          ull av = a64[i];
          ffma2(acc[i][0], av, bp0);
          ffma2(acc[i][1], av, bp1);
          ffma2(acc[i][2], av, bp2);
          ffma2(acc[i][3], av, bp3);
        }
      }
    }
  }

  float4 b4 = *(const float4*)&bias[nb + n0];
  #pragma unroll
  for (int i = 0; i < NP; i++){
    float r0[4], r1[4];
    #pragma unroll
    for (int j = 0; j < 4; j++) unpack2(acc[i][j], r0[j], r1[j]);
    #pragma unroll
    for (int h = 0; h < 2; h++){
      float* rr = h ? r1 : r0;
      int rv = vbase + m0 + 2*i + h;
      int vw = rv % rW; int t = rv / rW; int vh = t % rH; int vd = t / rH;
      int od = vd*stride + pd, oh = vh*stride + ph, ow = vw*stride + pw;
      size_t oo = (size_t)((od*outH + oh)*outW + ow) * Cout + nb + n0;
      float4 res;
      res.x = rr[0] + b4.x; res.y = rr[1] + b4.y;
      res.z = rr[2] + b4.z; res.w = rr[3] + b4.w;
      if (relu){
        res.x = fmaxf(res.x, 0.f); res.y = fmaxf(res.y, 0.f);
        res.z = fmaxf(res.z, 0.f); res.w = fmaxf(res.w, 0.f);
      }
      *(float4*)&out[oo] = res;
    }
  }
}

// ---------------------------------------------------------------------------
// ROUND-3 PROVEN KERNEL (verbatim): stride-1 C=128 + ReLU (L4).
// ---------------------------------------------------------------------------
template<int DIM>
__global__ __launch_bounds__(256) void deconv_s1r(
    const float* __restrict__ x, const float* __restrict__ w,
    const float* __restrict__ bias, float* __restrict__ out)
{
  constexpr int C  = 128;
  constexpr int BM = 128;
  constexpr int BK = 16;

  __shared__ float As[BK][BM];
  __shared__ float Bs[BK][C];
  __shared__ int   offs[BM];

  const int tid = threadIdx.x;
  const int vbase = blockIdx.x * BM;
  const int mg = tid >> 4;
  const int ng = tid & 15;
  const int m0 = mg * 8;

  int md, mh, mw;
  {
    int rv = vbase + (tid & (BM-1));
    mw = rv & (DIM-1); int t = rv / DIM; mh = t & (DIM-1); md = t / DIM;
  }

  ull acc[4][8];
  #pragma unroll
  for (int i = 0; i < 4; i++)
    #pragma unroll
    for (int j = 0; j < 8; j++) acc[i][j] = 0ull;

  for (int tap = 0; tap < 27; tap++){
    const int kw = tap % 3, kh = (tap / 3) % 3, kd = tap / 9;
    const float* wt = w + tap * C * C;

    __syncthreads();
    if (tid < BM){
      int id = md + kd - 1, ih = mh + kh - 1, iw = mw + kw - 1;
      bool v = (unsigned)id < (unsigned)DIM &&
               (unsigned)ih < (unsigned)DIM &&
               (unsigned)iw < (unsigned)DIM;
      offs[tid] = v ? ((id*DIM + ih)*DIM + iw) * C : -1;
    }

    for (int c0 = 0; c0 < C; c0 += BK){
      __syncthreads();
      #pragma unroll
      for (int idx = tid; idx < BM*4; idx += 256){
        int v = idx >> 2, q = idx & 3;
        int o = offs[v];
        float4 val = make_float4(0.f, 0.f, 0.f, 0.f);
        if (o >= 0) val = *(const float4*)(x + o + c0 + q*4);
        As[q*4+0][v] = val.x; As[q*4+1][v] = val.y;
        As[q*4+2][v] = val.z; As[q*4+3][v] = val.w;
      }
      #pragma unroll
      for (int idx = tid; idx < BK*(C/4); idx += 256){
        int r = idx >> 5, c4 = (idx & 31) * 4;
        *(float4*)&Bs[r][c4] = *(const float4*)(wt + (c0 + r)*C + c4);
      }
      __syncthreads();
      #pragma unroll
      for (int kk = 0; kk < BK; kk++){
        float4 a0 = *(const float4*)&As[kk][m0];
        float4 a1 = *(const float4*)&As[kk][m0 + 4];
        ull av[4];
        av[0] = pack2(a0.x, a0.y); av[1] = pack2(a0.z, a0.w);
        av[2] = pack2(a1.x, a1.y); av[3] = pack2(a1.z, a1.w);
        #pragma unroll
        for (int j = 0; j < 4; j++){
          float2 bv = *(const float2*)&Bs[kk][2*(ng + j*16)];
          ull b0 = pack2(bv.x, bv.x);
          ull b1 = pack2(bv.y, bv.y);
          #pragma unroll
          for (int i = 0; i < 4; i++){
            ffma2(acc[i][2*j+0], av[i], b0);
            ffma2(acc[i][2*j+1], av[i], b1);
          }
        }
      }
    }
  }

  float2 bb[4];
  #pragma unroll
  for (int j = 0; j < 4; j++)
    bb[j] = *(const float2*)&bias[2*(ng + j*16)];

  #pragma unroll
  for (int i = 0; i < 4; i++){
    float v0[8], v1[8];
    #pragma unroll
    for (int t = 0; t < 8; t++) unpack2(acc[i][t], v0[t], v1[t]);
    #pragma unroll
    for (int h = 0; h < 2; h++){
      float* vv = h ? v1 : v0;
      size_t oo = (size_t)(vbase + m0 + 2*i + h) * C;
      #pragma unroll
      for (int j = 0; j < 4; j++){
        float2 r;
        r.x = fmaxf(vv[2*j+0] + bb[j].x, 0.f);
        r.y = fmaxf(vv[2*j+1] + bb[j].y, 0.f);
        *(float2*)&out[oo + 2*(ng + j*16)] = r;
      }
    }
  }
}

// ---------------------------------------------------------------------------
// Fused L5+L6 path tables (R6-proven).
// ---------------------------------------------------------------------------
__device__ __constant__ int c_np[2][3]   = {{2,2,0},{1,3,1}};
__device__ __constant__ int c_k1[2][3][3] = {{{1,0,0},{2,1,0},{0,0,0}},
                                             {{0,0,0},{2,1,0},{2,0,0}}};
__device__ __constant__ int c_k2[2][3][3] = {{{0,1,0},{1,2,0},{0,0,0}},
                                             {{0,0,0},{0,1,2},{2,0,0}}};

// P1 (R6-proven, verbatim): Wp[k1][k2][ci][co]
__global__ __launch_bounds__(256) void p1_wp(
    const float* __restrict__ w2, const float* __restrict__ w20)
{
  int t = blockIdx.x * 256 + threadIdx.x;
  if (t >= 27*27*128) return;
  int ci = t & 127;
  int k2l = (t >> 7) % 27;
  int k1l = t / (27*128);
  const float* a = w2 + ((size_t)k1l*128 + ci) * 64;
  const float* b = w20 + (size_t)k2l * 64 * 3;
  float s0 = 0.f, s1 = 0.f, s2 = 0.f;
  #pragma unroll 4
  for (int cm = 0; cm < 64; cm++){
    float av = a[cm];
    s0 = fmaf(av, b[cm*3+0], s0);
    s1 = fmaf(av, b[cm*3+1], s1);
    s2 = fmaf(av, b[cm*3+2], s2);
  }
  float* o = g_Wp + (size_t)t * 3;
  o[0] = s0; o[1] = s1; o[2] = s2;
}

// P2 (R6 math, NEW ci-major layout): Weff[pz][dxl][co][ci]
__global__ __launch_bounds__(256) void p2_weff()
{
  int t = blockIdx.x * 256 + threadIdx.x;
  if (t >= 8*27*128) return;
  int ci = t & 127;
  int dxl = (t >> 7) % 27;
  int pz = t / (27*128);
  int jd = dxl / 9, jh = (dxl / 3) % 3, jw = dxl % 3;
  int pd = (pz >> 2) & 1, ph = (pz >> 1) & 1, pw = pz & 1;
  int nd = c_np[pd][jd], nh = c_np[ph][jh], nw = c_np[pw][jw];
  float s0 = 0.f, s1 = 0.f, s2 = 0.f;
  for (int a = 0; a < nd; a++)
  for (int b = 0; b < nh; b++)
  for (int c = 0; c < nw; c++){
    int k1l = (c_k1[pd][jd][a]*3 + c_k1[ph][jh][b])*3 + c_k1[pw][jw][c];
    int k2l = (c_k2[pd][jd][a]*3 + c_k2[ph][jh][b])*3 + c_k2[pw][jw][c];
    const float* wp = g_Wp + ((size_t)(k1l*27 + k2l)*128 + ci)*3;
    s0 += wp[0]; s1 += wp[1]; s2 += wp[2];
  }
  float* o = g_Weff + (size_t)(pz*27 + dxl) * 3 * 128;
  o[0*128 + ci] = s0;
  o[1*128 + ci] = s1;
  o[2*128 + ci] = s2;
}

// P3 (R6-proven, verbatim)
__global__ void p3_bias(const float* __restrict__ w20,
                        const float* __restrict__ b2,
                        const float* __restrict__ b20)
{
  int tid = threadIdx.x;
  if (tid < 81){
    int k2 = tid / 3, co = tid % 3;
    float s = 0.f;
    for (int cm = 0; cm < 64; cm++)
      s = fmaf(w20[(k2*64+cm)*3+co], b2[cm], s);
    g_bconv[tid] = s;
  }
  __syncthreads();
  if (tid < 3){
    float s = b20[tid];
    for (int k2 = 0; k2 < 27; k2++) s += g_bconv[k2*3+tid];
    g_btot[tid] = s;
  }
}

// ---------------------------------------------------------------------------
// NEW (round 7) fused L5+L6 consumer: direct conv, no SMEM staging.
// One warp per (reduced row (rd,rh), 8-voxel rw segment); single parity per
// block (gridDim.z = 8). Lanes split ci as pairs {2*lane, 2*lane+1} and
// {+64}: x and Weff read as coalesced LDG.64, consumed directly by ffma2
// (zero packs, zero LDS). 24 f32x2 accumulators (8 rw x 3 couts).
// Weights hoisted per tap. Butterfly-reduce over the 32 ci-lanes + bias.
// Boundary planes are overwritten exactly by fix56 (R6-proven).
// ---------------------------------------------------------------------------
__global__ __launch_bounds__(256) void fused56b(
    const float* __restrict__ x, float* __restrict__ out)
{
  const int wid  = threadIdx.x >> 5;
  const int lane = threadIdx.x & 31;
  const int pz = blockIdx.z;
  const int pd = (pz >> 2) & 1, ph = (pz >> 1) & 1, pw = pz & 1;
  const int wg  = blockIdx.x * 8 + wid;   // 0..4095 per parity
  const int seg = wg & 3;
  const int row = wg >> 2;                // 0..1023
  const int rd = row >> 5, rh = row & 31;
  const int rw0 = seg * 8;
  const int l2 = 2 * lane;

  ull acc[8][3];
  #pragma unroll
  for (int r = 0; r < 8; r++)
    #pragma unroll
    for (int c = 0; c < 3; c++) acc[r][c] = 0ull;

  for (int jd = 0; jd <= 1 + pd; jd++){
    int id = rd + jd - 1;
    if ((unsigned)id >= 32u) continue;
    for (int jh = 0; jh <= 1 + ph; jh++){
      int ih = rh + jh - 1;
      if ((unsigned)ih >= 32u) continue;
      const float* xrow = x + (size_t)((id*32 + ih)*32) * 128;
      for (int jw = 0; jw <= 1 + pw; jw++){
        const int dxl = jd*9 + jh*3 + jw;
        const float* Wt = g_Weff + (size_t)(pz*27 + dxl) * 3 * 128;
        ull w00 = *(const ull*)(Wt +   0 + l2);
        ull w01 = *(const ull*)(Wt +  64 + l2);
        ull w10 = *(const ull*)(Wt + 128 + l2);
        ull w11 = *(const ull*)(Wt + 192 + l2);
        ull w20 = *(const ull*)(Wt + 256 + l2);
        ull w21 = *(const ull*)(Wt + 320 + l2);
        #pragma unroll
        for (int r = 0; r < 8; r++){
          int iw = rw0 + r + jw - 1;
          if ((unsigned)iw < 32u){
            const float* xp = xrow + iw * 128;
            ull x0 = *(const ull*)(xp + l2);
            ull x1 = *(const ull*)(xp + 64 + l2);
            ffma2(acc[r][0], x0, w00); ffma2(acc[r][0], x1, w01);
            ffma2(acc[r][1], x0, w10); ffma2(acc[r][1], x1, w11);
            ffma2(acc[r][2], x0, w20); ffma2(acc[r][2], x1, w21);
          }
        }
      }
    }
  }

  const float bt0 = g_btot[0], bt1 = g_btot[1], bt2 = g_btot[2];
  const int od = 2*rd + pd, oh = 2*rh + ph;

  #pragma unroll
  for (int r = 0; r < 8; r++){
    float s0, s1, s2;
    {
      float a, b;
      unpack2(acc[r][0], a, b); s0 = a + b;
      unpack2(acc[r][1], a, b); s1 = a + b;
      unpack2(acc[r][2], a, b); s2 = a + b;
    }
    #pragma unroll
    for (int sh = 16; sh > 0; sh >>= 1){
      s0 += __shfl_xor_sync(0xffffffffu, s0, sh);
      s1 += __shfl_xor_sync(0xffffffffu, s1, sh);
      s2 += __shfl_xor_sync(0xffffffffu, s2, sh);
    }
    if (lane == 0){
      int ow = 2*(rw0 + r) + pw;
      float* op = out + (size_t)((od*64 + oh)*64 + ow) * 3;
      op[0] = s0 + bt0;
      op[1] = s1 + bt1;
      op[2] = s2 + bt2;
    }
  }
}

// ---------------------------------------------------------------------------
// fix56 (R6-proven, verbatim): exact recompute of the 6 boundary planes.
// ---------------------------------------------------------------------------
__global__ __launch_bounds__(256) void fix56(
    const float* __restrict__ x, const float* __restrict__ b20,
    float* __restrict__ out)
{
  int idx = blockIdx.x * 256 + threadIdx.x;
  if (idx >= 6*4096) return;
  int plane = idx / 4096, r = idx % 4096;
  int a = r / 64, b = r % 64;
  int od, oh, ow;
  if      (plane == 0){ od = 0;  oh = a; ow = b; }
  else if (plane == 1){ od = 63; oh = a; ow = b; }
  else if (plane == 2){ oh = 0;  od = a; ow = b; if (od==0||od==63) return; }
  else if (plane == 3){ oh = 63; od = a; ow = b; if (od==0||od==63) return; }
  else if (plane == 4){ ow = 0;  od = a; oh = b; if (od==0||od==63||oh==0||oh==63) return; }
  else               { ow = 63; od = a; oh = b; if (od==0||od==63||oh==0||oh==63) return; }

  float acc0 = __ldg(&b20[0]), acc1 = __ldg(&b20[1]), acc2 = __ldg(&b20[2]);

  for (int k2d = 0; k2d < 3; k2d++){
    int md = od + k2d - 1; if ((unsigned)md >= 64u) continue;
    int pmd = md & 1, rd = (md - pmd) >> 1;
    int n_d = pmd ? 1 : 2;
    int k1d[2], ixd[2];
    if (pmd){ k1d[0] = 1; ixd[0] = rd; }
    else    { k1d[0] = 0; ixd[0] = rd - 1; k1d[1] = 2; ixd[1] = rd; }
    for (int k2h = 0; k2h < 3; k2h++){
      int mh = oh + k2h - 1; if ((unsigned)mh >= 64u) continue;
      int pmh = mh & 1, rh = (mh - pmh) >> 1;
      int n_h = pmh ? 1 : 2;
      int k1h[2], ixh[2];
      if (pmh){ k1h[0] = 1; ixh[0] = rh; }
      else    { k1h[0] = 0; ixh[0] = rh - 1; k1h[1] = 2; ixh[1] = rh; }
      for (int k2w = 0; k2w < 3; k2w++){
        int mw = ow + k2w - 1; if ((unsigned)mw >= 64u) continue;
        int pmw = mw & 1, rw = (mw - pmw) >> 1;
        int n_w = pmw ? 1 : 2;
        int k1w[2], ixw[2];
        if (pmw){ k1w[0] = 1; ixw[0] = rw; }
        else    { k1w[0] = 0; ixw[0] = rw - 1; k1w[1] = 2; ixw[1] = rw; }

        int k2l = (k2d*3 + k2h)*3 + k2w;
        acc0 += g_bconv[k2l*3+0];
        acc1 += g_bconv[k2l*3+1];
        acc2 += g_bconv[k2l*3+2];

        for (int ia = 0; ia < n_d; ia++){
          if ((unsigned)ixd[ia] >= 32u) continue;
          for (int ib = 0; ib < n_h; ib++){
            if ((unsigned)ixh[ib] >= 32u) continue;
            for (int ic = 0; ic < n_w; ic++){
              if ((unsigned)ixw[ic] >= 32u) continue;
              int k1l = (k1d[ia]*3 + k1h[ib])*3 + k1w[ic];
              const float* wp = g_Wp + (size_t)(k1l*27 + k2l)*384;
              const float* xp = x + (size_t)((ixd[ia]*32 + ixh[ib])*32 + ixw[ic])*128;
              #pragma unroll 4
              for (int c4 = 0; c4 < 32; c4++){
                float4 xv = *(const float4*)(xp + c4*4);
                const float* w4 = wp + c4*12;
                acc0 = fmaf(xv.x, w4[0],  acc0);
                acc1 = fmaf(xv.x, w4[1],  acc1);
                acc2 = fmaf(xv.x, w4[2],  acc2);
                acc0 = fmaf(xv.y, w4[3],  acc0);
                acc1 = fmaf(xv.y, w4[4],  acc1);
                acc2 = fmaf(xv.y, w4[5],  acc2);
                acc0 = fmaf(xv.z, w4[6],  acc0);
                acc1 = fmaf(xv.z, w4[7],  acc1);
                acc2 = fmaf(xv.z, w4[8],  acc2);
                acc0 = fmaf(xv.w, w4[9],  acc0);
                acc1 = fmaf(xv.w, w4[10], acc1);
                acc2 = fmaf(xv.w, w4[11], acc2);
              }
            }
          }
        }
      }
    }
  }

  float* op = out + (size_t)((od*64 + oh)*64 + ow) * 3;
  op[0] = acc0; op[1] = acc1; op[2] = acc2;
}

// ---------------------------------------------------------------------------
// kernel_launch
// ---------------------------------------------------------------------------
extern "C" void kernel_launch(void* const* d_in, const int* in_sizes, int n_in,
                              void* d_out, int out_size)
{
  (void)in_sizes; (void)n_in; (void)out_size;
  const float* x   = (const float*)d_in[0];
  const float* w0  = (const float*)d_in[1];
  const float* b0  = (const float*)d_in[2];
  const float* w00 = (const float*)d_in[3];
  const float* b00 = (const float*)d_in[4];
  const float* w1  = (const float*)d_in[5];
  const float* b1  = (const float*)d_in[6];
  const float* w10 = (const float*)d_in[7];
  const float* b10 = (const float*)d_in[8];
  const float* w2  = (const float*)d_in[9];
  const float* b2  = (const float*)d_in[10];
  const float* w20 = (const float*)d_in[11];
  const float* b20 = (const float*)d_in[12];
  float* out = (float*)d_out;

  float *bufA = nullptr, *bufB = nullptr;
  cudaGetSymbolAddress((void**)&bufA, g_bufA);
  cudaGetSymbolAddress((void**)&bufB, g_bufB);

  // Precompute fused L5+L6 weights
  p1_wp<<<(27*27*128 + 255)/256, 256>>>(w2, w20);
  p2_weff<<<(8*27*128 + 255)/256, 256>>>();
  p3_bias<<<1, 128>>>(w20, b2, b20);

  // L1: deconv0 s2: x(8^3,128) -> bufA(16^3,128)   [R1 proven]
  {
    dim3 g(512/32, 128/64, 8);
    deconv_gemm<32,2><<<g, 256>>>(x,  w0,  b0,  bufA,
                                  8,8,8,128,  16,16,16,128, 2, 0);
  }
  // L2: deconv0_0 s1 + relu: bufA -> bufB(16^3,128)   [R1 proven]
  {
    dim3 g(4096/32, 128/64, 1);
    deconv_gemm<32,2><<<g, 256>>>(bufA, w00, b00, bufB,
                                  16,16,16,128, 16,16,16,128, 1, 1);
  }
  // L3: deconv1 s2: bufB -> bufA(32^3,128)   [R1 proven]
  {
    dim3 g(4096/128, 128/64, 8);
    deconv_gemm<128,8><<<g, 256>>>(bufB, w1, b1, bufA,
                                   16,16,16,128, 32,32,32,128, 2, 0);
  }
  // L4: deconv1_0 s1 + relu: bufA -> bufB(32^3,128)   [R3 proven]
  deconv_s1r<32><<<32768/128, 256>>>(bufA, w10, b10, bufB);

  // Fused L5+L6: bufB(32^3,128) -> out(64^3,3)   [NEW direct-conv consumer]
  {
    dim3 g(512, 1, 8);
    fused56b<<<g, 256>>>(bufB, out);
  }
  // Exact boundary fix (R6 proven)
  fix56<<<96, 256>>>(bufB, b20, out);
}

// round 8
// speedup vs baseline: 2.0039x; 1.4378x over previous
#include <cuda_runtime.h>

// ---------------------------------------------------------------------------
// Static scratch (no allocation allowed)
// ---------------------------------------------------------------------------
__device__ float g_bufA[16777216];
__device__ float g_bufB[4194304];
__device__ float g_Wp[279936];      // [k1lin 27][k2lin 27][ci 128][co 3]
__device__ float g_WpT[279936];     // [k1lin 27][k2lin 27][co 3][ci 128]
__device__ float g_Weff[110592];    // [pz 8][dxlin 27][co 3][ci 128]
__device__ float g_bconv[81];       // [k2lin 27][co 3]
__device__ float g_btot[3];

typedef unsigned long long ull;

// ---------------------------------------------------------------------------
// f32x2 packed helpers
// ---------------------------------------------------------------------------
__device__ __forceinline__ ull pack2(float x, float y){
  ull r; asm("mov.b64 %0, {%1, %2};" : "=l"(r) : "f"(x), "f"(y)); return r;
}
__device__ __forceinline__ void unpack2(ull v, float& x, float& y){
  asm("mov.b64 {%0, %1}, %2;" : "=f"(x), "=f"(y) : "l"(v));
}
__device__ __forceinline__ void ffma2(ull& acc, ull a, ull b){
  asm("fma.rn.f32x2 %0, %1, %2, %0;" : "+l"(acc) : "l"(a), "l"(b));
}

// ---------------------------------------------------------------------------
// ROUND-1 PROVEN KERNEL (verbatim): generic transposed-conv implicit GEMM.
// ---------------------------------------------------------------------------
template<int BM, int TM>
__global__ __launch_bounds__(256) void deconv_gemm(
    const float* __restrict__ x, const float* __restrict__ w,
    const float* __restrict__ bias, float* __restrict__ out,
    int inD, int inH, int inW, int Cin,
    int outD, int outH, int outW, int Cout,
    int stride, int relu)
{
  constexpr int BN = 64;
  constexpr int BK = 16;
  constexpr int NP = TM / 2;

  __shared__ float As[BK][BM];
  __shared__ float Bs[BK][BN];
  __shared__ int   offs[BM];

  const int tid = threadIdx.x;
  const int pz = blockIdx.z;
  const int pd = (pz >> 2) & 1, ph = (pz >> 1) & 1, pw = pz & 1;
  const int rH = outH / stride, rW = outW / stride;
  const int nb = blockIdx.y * BN;
  const int vbase = blockIdx.x * BM;

  int md = 0, mh = 0, mw = 0;
  if (tid < BM) {
    int rv = vbase + tid;
    mw = rv % rW; int t = rv / rW; mh = t % rH; md = t / rH;
  }

  int nkd, kdL[3], ddL[3];
  int nkh, khL[3], dhL[3];
  int nkw, kwL[3], dwL[3];
  auto mk = [&](int p, int& n, int* kL, int* dL){
    if (stride == 1){ n = 3; kL[0]=0; kL[1]=1; kL[2]=2; dL[0]=-1; dL[1]=0; dL[2]=1; }
    else if (p == 0){ n = 2; kL[0]=0; kL[1]=2; dL[0]=-1; dL[1]=0; }
    else            { n = 1; kL[0]=1; dL[0]=0; }
  };
  mk(pd, nkd, kdL, ddL);
  mk(ph, nkh, khL, dhL);
  mk(pw, nkw, kwL, dwL);

  const int mg = tid >> 4, ng = tid & 15;
  const int m0 = mg * TM, n0 = ng * 4;

  ull acc[NP][4];
  #pragma unroll
  for (int i = 0; i < NP; i++)
    #pragma unroll
    for (int j = 0; j < 4; j++) acc[i][j] = 0ull;

  for (int ia = 0; ia < nkd; ia++)
  for (int ib = 0; ib < nkh; ib++)
  for (int ic = 0; ic < nkw; ic++){
    const int tap = (kdL[ia]*3 + khL[ib])*3 + kwL[ic];
    const float* wt = w + (size_t)tap * Cin * Cout + nb;

    __syncthreads();
    if (tid < BM){
      int id = md + ddL[ia];
      int ih = mh + dhL[ib];
      int iw = mw + dwL[ic];
      bool v = (unsigned)id < (unsigned)inD &&
               (unsigned)ih < (unsigned)inH &&
               (unsigned)iw < (unsigned)inW;
      offs[tid] = v ? ((id*inH + ih)*inW + iw) * Cin : -1;
    }

    for (int c0 = 0; c0 < Cin; c0 += BK){
      __syncthreads();
      for (int idx = tid; idx < BM*4; idx += 256){
        int v = idx >> 2, c4 = (idx & 3) * 4;
        int o = offs[v];
        float4 val = make_float4(0.f, 0.f, 0.f, 0.f);
        if (o >= 0) val = *(const float4*)(x + o + c0 + c4);
        As[c4+0][v] = val.x; As[c4+1][v] = val.y;
        As[c4+2][v] = val.z; As[c4+3][v] = val.w;
      }
      {
        int r = tid >> 4, col = (tid & 15) * 4;
        float4 bv = *(const float4*)(wt + (size_t)(c0 + r) * Cout + col);
        *(float4*)&Bs[r][col] = bv;
      }
      __syncthreads();
      #pragma unroll
      for (int kk = 0; kk < BK; kk++){
        const ull* a64 = (const ull*)&As[kk][m0];
        float4 bv = *(const float4*)&Bs[kk][n0];
        ull bp0 = pack2(bv.x, bv.x);
        ull bp1 = pack2(bv.y, bv.y);
        ull bp2 = pack2(bv.z, bv.z);
        ull bp3 = pack2(bv.w, bv.w);
        #pragma unroll
        for (int i = 0; i < NP; i++){
          ull av = a64[i];
          ffma2(acc[i][0], av, bp0);
          ffma2(acc[i][1], av, bp1);
          ffma2(acc[i][2], av, bp2);
          ffma2(acc[i][3], av, bp3);
        }
      }
    }
  }

  float4 b4 = *(const float4*)&bias[nb + n0];
  #pragma unroll
  for (int i = 0; i < NP; i++){
    float r0[4], r1[4];
    #pragma unroll
    for (int j = 0; j < 4; j++) unpack2(acc[i][j], r0[j], r1[j]);
    #pragma unroll
    for (int h = 0; h < 2; h++){
      float* rr = h ? r1 : r0;
      int rv = vbase + m0 + 2*i + h;
      int vw = rv % rW; int t = rv / rW; int vh = t % rH; int vd = t / rH;
      int od = vd*stride + pd, oh = vh*stride + ph, ow = vw*stride + pw;
      size_t oo = (size_t)((od*outH + oh)*outW + ow) * Cout + nb + n0;
      float4 res;
      res.x = rr[0] + b4.x; res.y = rr[1] + b4.y;
      res.z = rr[2] + b4.z; res.w = rr[3] + b4.w;
      if (relu){
        res.x = fmaxf(res.x, 0.f); res.y = fmaxf(res.y, 0.f);
        res.z = fmaxf(res.z, 0.f); res.w = fmaxf(res.w, 0.f);
      }
      *(float4*)&out[oo] = res;
    }
  }
}

// ---------------------------------------------------------------------------
// ROUND-3 PROVEN KERNEL (verbatim): stride-1 C=128 + ReLU (L4).
// ---------------------------------------------------------------------------
template<int DIM>
__global__ __launch_bounds__(256) void deconv_s1r(
    const float* __restrict__ x, const float* __restrict__ w,
    const float* __restrict__ bias, float* __restrict__ out)
{
  constexpr int C  = 128;
  constexpr int BM = 128;
  constexpr int BK = 16;

  __shared__ float As[BK][BM];
  __shared__ float Bs[BK][C];
  __shared__ int   offs[BM];

  const int tid = threadIdx.x;
  const int vbase = blockIdx.x * BM;
  const int mg = tid >> 4;
  const int ng = tid & 15;
  const int m0 = mg * 8;

  int md, mh, mw;
  {
    int rv = vbase + (tid & (BM-1));
    mw = rv & (DIM-1); int t = rv / DIM; mh = t & (DIM-1); md = t / DIM;
  }

  ull acc[4][8];
  #pragma unroll
  for (int i = 0; i < 4; i++)
    #pragma unroll
    for (int j = 0; j < 8; j++) acc[i][j] = 0ull;

  for (int tap = 0; tap < 27; tap++){
    const int kw = tap % 3, kh = (tap / 3) % 3, kd = tap / 9;
    const float* wt = w + tap * C * C;

    __syncthreads();
    if (tid < BM){
      int id = md + kd - 1, ih = mh + kh - 1, iw = mw + kw - 1;
      bool v = (unsigned)id < (unsigned)DIM &&
               (unsigned)ih < (unsigned)DIM &&
               (unsigned)iw < (unsigned)DIM;
      offs[tid] = v ? ((id*DIM + ih)*DIM + iw) * C : -1;
    }

    for (int c0 = 0; c0 < C; c0 += BK){
      __syncthreads();
      #pragma unroll
      for (int idx = tid; idx < BM*4; idx += 256){
        int v = idx >> 2, q = idx & 3;
        int o = offs[v];
        float4 val = make_float4(0.f, 0.f, 0.f, 0.f);
        if (o >= 0) val = *(const float4*)(x + o + c0 + q*4);
        As[q*4+0][v] = val.x; As[q*4+1][v] = val.y;
        As[q*4+2][v] = val.z; As[q*4+3][v] = val.w;
      }
      #pragma unroll
      for (int idx = tid; idx < BK*(C/4); idx += 256){
        int r = idx >> 5, c4 = (idx & 31) * 4;
        *(float4*)&Bs[r][c4] = *(const float4*)(wt + (c0 + r)*C + c4);
      }
      __syncthreads();
      #pragma unroll
      for (int kk = 0; kk < BK; kk++){
        float4 a0 = *(const float4*)&As[kk][m0];
        float4 a1 = *(const float4*)&As[kk][m0 + 4];
        ull av[4];
        av[0] = pack2(a0.x, a0.y); av[1] = pack2(a0.z, a0.w);
        av[2] = pack2(a1.x, a1.y); av[3] = pack2(a1.z, a1.w);
        #pragma unroll
        for (int j = 0; j < 4; j++){
          float2 bv = *(const float2*)&Bs[kk][2*(ng + j*16)];
          ull b0 = pack2(bv.x, bv.x);
          ull b1 = pack2(bv.y, bv.y);
          #pragma unroll
          for (int i = 0; i < 4; i++){
            ffma2(acc[i][2*j+0], av[i], b0);
            ffma2(acc[i][2*j+1], av[i], b1);
          }
        }
      }
    }
  }

  float2 bb[4];
  #pragma unroll
  for (int j = 0; j < 4; j++)
    bb[j] = *(const float2*)&bias[2*(ng + j*16)];

  #pragma unroll
  for (int i = 0; i < 4; i++){
    float v0[8], v1[8];
    #pragma unroll
    for (int t = 0; t < 8; t++) unpack2(acc[i][t], v0[t], v1[t]);
    #pragma unroll
    for (int h = 0; h < 2; h++){
      float* vv = h ? v1 : v0;
      size_t oo = (size_t)(vbase + m0 + 2*i + h) * C;
      #pragma unroll
      for (int j = 0; j < 4; j++){
        float2 r;
        r.x = fmaxf(vv[2*j+0] + bb[j].x, 0.f);
        r.y = fmaxf(vv[2*j+1] + bb[j].y, 0.f);
        *(float2*)&out[oo + 2*(ng + j*16)] = r;
      }
    }
  }
}

// ---------------------------------------------------------------------------
// Fused L5+L6 path tables (R6-proven).
// ---------------------------------------------------------------------------
__device__ __constant__ int c_np[2][3]   = {{2,2,0},{1,3,1}};
__device__ __constant__ int c_k1[2][3][3] = {{{1,0,0},{2,1,0},{0,0,0}},
                                             {{0,0,0},{2,1,0},{2,0,0}}};
__device__ __constant__ int c_k2[2][3][3] = {{{0,1,0},{1,2,0},{0,0,0}},
                                             {{0,0,0},{0,1,2},{2,0,0}}};

// P1 (R6-proven, verbatim): Wp[k1][k2][ci][co]
__global__ __launch_bounds__(256) void p1_wp(
    const float* __restrict__ w2, const float* __restrict__ w20)
{
  int t = blockIdx.x * 256 + threadIdx.x;
  if (t >= 27*27*128) return;
  int ci = t & 127;
  int k2l = (t >> 7) % 27;
  int k1l = t / (27*128);
  const float* a = w2 + ((size_t)k1l*128 + ci) * 64;
  const float* b = w20 + (size_t)k2l * 64 * 3;
  float s0 = 0.f, s1 = 0.f, s2 = 0.f;
  #pragma unroll 4
  for (int cm = 0; cm < 64; cm++){
    float av = a[cm];
    s0 = fmaf(av, b[cm*3+0], s0);
    s1 = fmaf(av, b[cm*3+1], s1);
    s2 = fmaf(av, b[cm*3+2], s2);
  }
  float* o = g_Wp + (size_t)t * 3;
  o[0] = s0; o[1] = s1; o[2] = s2;
}

// NEW: transpose Wp -> WpT[k1,k2][co][ci] (ci-contiguous for fix56w)
__global__ __launch_bounds__(256) void p1t_wpT()
{
  int t = blockIdx.x * 256 + threadIdx.x;
  if (t >= 279936) return;
  int ci = t & 127;
  int co = (t >> 7) % 3;
  int kk = t / 384;
  g_WpT[(size_t)kk*384 + co*128 + ci] = g_Wp[((size_t)kk*128 + ci)*3 + co];
}

// P2 (R7-proven, verbatim): Weff[pz][dxl][co][ci]
__global__ __launch_bounds__(256) void p2_weff()
{
  int t = blockIdx.x * 256 + threadIdx.x;
  if (t >= 8*27*128) return;
  int ci = t & 127;
  int dxl = (t >> 7) % 27;
  int pz = t / (27*128);
  int jd = dxl / 9, jh = (dxl / 3) % 3, jw = dxl % 3;
  int pd = (pz >> 2) & 1, ph = (pz >> 1) & 1, pw = pz & 1;
  int nd = c_np[pd][jd], nh = c_np[ph][jh], nw = c_np[pw][jw];
  float s0 = 0.f, s1 = 0.f, s2 = 0.f;
  for (int a = 0; a < nd; a++)
  for (int b = 0; b < nh; b++)
  for (int c = 0; c < nw; c++){
    int k1l = (c_k1[pd][jd][a]*3 + c_k1[ph][jh][b])*3 + c_k1[pw][jw][c];
    int k2l = (c_k2[pd][jd][a]*3 + c_k2[ph][jh][b])*3 + c_k2[pw][jw][c];
    const float* wp = g_Wp + ((size_t)(k1l*27 + k2l)*128 + ci)*3;
    s0 += wp[0]; s1 += wp[1]; s2 += wp[2];
  }
  float* o = g_Weff + (size_t)(pz*27 + dxl) * 3 * 128;
  o[0*128 + ci] = s0;
  o[1*128 + ci] = s1;
  o[2*128 + ci] = s2;
}

// P3 (R6-proven, verbatim)
__global__ void p3_bias(const float* __restrict__ w20,
                        const float* __restrict__ b2,
                        const float* __restrict__ b20)
{
  int tid = threadIdx.x;
  if (tid < 81){
    int k2 = tid / 3, co = tid % 3;
    float s = 0.f;
    for (int cm = 0; cm < 64; cm++)
      s = fmaf(w20[(k2*64+cm)*3+co], b2[cm], s);
    g_bconv[tid] = s;
  }
  __syncthreads();
  if (tid < 3){
    float s = b20[tid];
    for (int k2 = 0; k2 < 27; k2++) s += g_bconv[k2*3+tid];
    g_btot[tid] = s;
  }
}

// ---------------------------------------------------------------------------
// Fused L5+L6 consumer (R7-proven, verbatim): direct conv, no SMEM staging.
// ---------------------------------------------------------------------------
__global__ __launch_bounds__(256) void fused56b(
    const float* __restrict__ x, float* __restrict__ out)
{
  const int wid  = threadIdx.x >> 5;
  const int lane = threadIdx.x & 31;
  const int pz = blockIdx.z;
  const int pd = (pz >> 2) & 1, ph = (pz >> 1) & 1, pw = pz & 1;
  const int wg  = blockIdx.x * 8 + wid;
  const int seg = wg & 3;
  const int row = wg >> 2;
  const int rd = row >> 5, rh = row & 31;
  const int rw0 = seg * 8;
  const int l2 = 2 * lane;

  ull acc[8][3];
  #pragma unroll
  for (int r = 0; r < 8; r++)
    #pragma unroll
    for (int c = 0; c < 3; c++) acc[r][c] = 0ull;

  for (int jd = 0; jd <= 1 + pd; jd++){
    int id = rd + jd - 1;
    if ((unsigned)id >= 32u) continue;
    for (int jh = 0; jh <= 1 + ph; jh++){
      int ih = rh + jh - 1;
      if ((unsigned)ih >= 32u) continue;
      const float* xrow = x + (size_t)((id*32 + ih)*32) * 128;
      for (int jw = 0; jw <= 1 + pw; jw++){
        const int dxl = jd*9 + jh*3 + jw;
        const float* Wt = g_Weff + (size_t)(pz*27 + dxl) * 3 * 128;
        ull w00 = *(const ull*)(Wt +   0 + l2);
        ull w01 = *(const ull*)(Wt +  64 + l2);
        ull w10 = *(const ull*)(Wt + 128 + l2);
        ull w11 = *(const ull*)(Wt + 192 + l2);
        ull w20 = *(const ull*)(Wt + 256 + l2);
        ull w21 = *(const ull*)(Wt + 320 + l2);
        #pragma unroll
        for (int r = 0; r < 8; r++){
          int iw = rw0 + r + jw - 1;
          if ((unsigned)iw < 32u){
            const float* xp = xrow + iw * 128;
            ull x0 = *(const ull*)(xp + l2);
            ull x1 = *(const ull*)(xp + 64 + l2);
            ffma2(acc[r][0], x0, w00); ffma2(acc[r][0], x1, w01);
            ffma2(acc[r][1], x0, w10); ffma2(acc[r][1], x1, w11);
            ffma2(acc[r][2], x0, w20); ffma2(acc[r][2], x1, w21);
          }
        }
      }
    }
  }

  const float bt0 = g_btot[0], bt1 = g_btot[1], bt2 = g_btot[2];
  const int od = 2*rd + pd, oh = 2*rh + ph;

  #pragma unroll
  for (int r = 0; r < 8; r++){
    float s0, s1, s2;
    {
      float a, b;
      unpack2(acc[r][0], a, b); s0 = a + b;
      unpack2(acc[r][1], a, b); s1 = a + b;
      unpack2(acc[r][2], a, b); s2 = a + b;
    }
    #pragma unroll
    for (int sh = 16; sh > 0; sh >>= 1){
      s0 += __shfl_xor_sync(0xffffffffu, s0, sh);
      s1 += __shfl_xor_sync(0xffffffffu, s1, sh);
      s2 += __shfl_xor_sync(0xffffffffu, s2, sh);
    }
    if (lane == 0){
      int ow = 2*(rw0 + r) + pw;
      float* op = out + (size_t)((od*64 + oh)*64 + ow) * 3;
      op[0] = s0 + bt0;
      op[1] = s1 + bt1;
      op[2] = s2 + bt2;
    }
  }
}

// ---------------------------------------------------------------------------
// NEW (round 8): fix56w — same boundary math as R6-proven fix56, but one
// WARP per boundary voxel. Lanes split ci as pairs {2l,2l+1} and {+64};
// x and WpT read as coalesced LDG.64 feeding ffma2 directly. Butterfly
// reduce + bias at the end. 24576 warps (vs 24576 serial threads before).
// ---------------------------------------------------------------------------
__global__ __launch_bounds__(256) void fix56w(
    const float* __restrict__ x, const float* __restrict__ b20,
    float* __restrict__ out)
{
  const int gw = blockIdx.x * 8 + (threadIdx.x >> 5);
  const int lane = threadIdx.x & 31;
  const int l2 = 2 * lane;

  int plane = gw / 4096, r = gw % 4096;
  int a = r / 64, b = r % 64;
  int od, oh, ow;
  if      (plane == 0){ od = 0;  oh = a; ow = b; }
  else if (plane == 1){ od = 63; oh = a; ow = b; }
  else if (plane == 2){ oh = 0;  od = a; ow = b; if (od==0||od==63) return; }
  else if (plane == 3){ oh = 63; od = a; ow = b; if (od==0||od==63) return; }
  else if (plane == 4){ ow = 0;  od = a; oh = b; if (od==0||od==63||oh==0||oh==63) return; }
  else               { ow = 63; od = a; oh = b; if (od==0||od==63||oh==0||oh==63) return; }

  ull a0 = 0ull, a1 = 0ull, a2 = 0ull;
  float bias0 = __ldg(&b20[0]), bias1 = __ldg(&b20[1]), bias2 = __ldg(&b20[2]);

  for (int k2d = 0; k2d < 3; k2d++){
    int md = od + k2d - 1; if ((unsigned)md >= 64u) continue;
    int pmd = md & 1, rd = (md - pmd) >> 1;
    int n_d = pmd ? 1 : 2;
    int k1d[2], ixd[2];
    if (pmd){ k1d[0] = 1; ixd[0] = rd; }
    else    { k1d[0] = 0; ixd[0] = rd - 1; k1d[1] = 2; ixd[1] = rd; }
    for (int k2h = 0; k2h < 3; k2h++){
      int mh = oh + k2h - 1; if ((unsigned)mh >= 64u) continue;
      int pmh = mh & 1, rh = (mh - pmh) >> 1;
      int n_h = pmh ? 1 : 2;
      int k1h[2], ixh[2];
      if (pmh){ k1h[0] = 1; ixh[0] = rh; }
      else    { k1h[0] = 0; ixh[0] = rh - 1; k1h[1] = 2; ixh[1] = rh; }
      for (int k2w = 0; k2w < 3; k2w++){
        int mw = ow + k2w - 1; if ((unsigned)mw >= 64u) continue;
        int pmw = mw & 1, rw = (mw - pmw) >> 1;
        int n_w = pmw ? 1 : 2;
        int k1w[2], ixw[2];
        if (pmw){ k1w[0] = 1; ixw[0] = rw; }
        else    { k1w[0] = 0; ixw[0] = rw - 1; k1w[1] = 2; ixw[1] = rw; }

        int k2l = (k2d*3 + k2h)*3 + k2w;
        bias0 += g_bconv[k2l*3+0];
        bias1 += g_bconv[k2l*3+1];
        bias2 += g_bconv[k2l*3+2];

        for (int ia = 0; ia < n_d; ia++){
          if ((unsigned)ixd[ia] >= 32u) continue;
          for (int ib = 0; ib < n_h; ib++){
            if ((unsigned)ixh[ib] >= 32u) continue;
            for (int ic = 0; ic < n_w; ic++){
              if ((unsigned)ixw[ic] >= 32u) continue;
              int k1l = (k1d[ia]*3 + k1h[ib])*3 + k1w[ic];
              const float* wt = g_WpT + (size_t)(k1l*27 + k2l)*384;
              const float* xp = x + (size_t)((ixd[ia]*32 + ixh[ib])*32 + ixw[ic])*128;
              ull x0 = *(const ull*)(xp + l2);
              ull x1 = *(const ull*)(xp + 64 + l2);
              ffma2(a0, x0, *(const ull*)(wt +   0 + l2));
              ffma2(a0, x1, *(const ull*)(wt +  64 + l2));
              ffma2(a1, x0, *(const ull*)(wt + 128 + l2));
              ffma2(a1, x1, *(const ull*)(wt + 192 + l2));
              ffma2(a2, x0, *(const ull*)(wt + 256 + l2));
              ffma2(a2, x1, *(const ull*)(wt + 320 + l2));
            }
          }
        }
      }
    }
  }

  float s0, s1, s2;
  {
    float u, v;
    unpack2(a0, u, v); s0 = u + v;
    unpack2(a1, u, v); s1 = u + v;
    unpack2(a2, u, v); s2 = u + v;
  }
  #pragma unroll
  for (int sh = 16; sh > 0; sh >>= 1){
    s0 += __shfl_xor_sync(0xffffffffu, s0, sh);
    s1 += __shfl_xor_sync(0xffffffffu, s1, sh);
    s2 += __shfl_xor_sync(0xffffffffu, s2, sh);
  }
  if (lane == 0){
    float* op = out + (size_t)((od*64 + oh)*64 + ow) * 3;
    op[0] = s0 + bias0;
    op[1] = s1 + bias1;
    op[2] = s2 + bias2;
  }
}

// ---------------------------------------------------------------------------
// kernel_launch
// ---------------------------------------------------------------------------
extern "C" void kernel_launch(void* const* d_in, const int* in_sizes, int n_in,
                              void* d_out, int out_size)
{
  (void)in_sizes; (void)n_in; (void)out_size;
  const float* x   = (const float*)d_in[0];
  const float* w0  = (const float*)d_in[1];
  const float* b0  = (const float*)d_in[2];
  const float* w00 = (const float*)d_in[3];
  const float* b00 = (const float*)d_in[4];
  const float* w1  = (const float*)d_in[5];
  const float* b1  = (const float*)d_in[6];
  const float* w10 = (const float*)d_in[7];
  const float* b10 = (const float*)d_in[8];
  const float* w2  = (const float*)d_in[9];
  const float* b2  = (const float*)d_in[10];
  const float* w20 = (const float*)d_in[11];
  const float* b20 = (const float*)d_in[12];
  float* out = (float*)d_out;

  float *bufA = nullptr, *bufB = nullptr;
  cudaGetSymbolAddress((void**)&bufA, g_bufA);
  cudaGetSymbolAddress((void**)&bufB, g_bufB);

  // Precompute fused L5+L6 weights
  p1_wp<<<(27*27*128 + 255)/256, 256>>>(w2, w20);
  p1t_wpT<<<(279936 + 255)/256, 256>>>();
  p2_weff<<<(8*27*128 + 255)/256, 256>>>();
  p3_bias<<<1, 128>>>(w20, b2, b20);

  // L1: deconv0 s2: x(8^3,128) -> bufA(16^3,128)   [R1 proven]
  {
    dim3 g(512/32, 128/64, 8);
    deconv_gemm<32,2><<<g, 256>>>(x,  w0,  b0,  bufA,
                                  8,8,8,128,  16,16,16,128, 2, 0);
  }
  // L2: deconv0_0 s1 + relu: bufA -> bufB(16^3,128)   [R1 proven]
  {
    dim3 g(4096/32, 128/64, 1);
    deconv_gemm<32,2><<<g, 256>>>(bufA, w00, b00, bufB,
                                  16,16,16,128, 16,16,16,128, 1, 1);
  }
  // L3: deconv1 s2: bufB -> bufA(32^3,128)   [R1 proven]
  {
    dim3 g(4096/128, 128/64, 8);
    deconv_gemm<128,8><<<g, 256>>>(bufB, w1, b1, bufA,
                                   16,16,16,128, 32,32,32,128, 2, 0);
  }
  // L4: deconv1_0 s1 + relu: bufA -> bufB(32^3,128)   [R3 proven]
  deconv_s1r<32><<<32768/128, 256>>>(bufA, w10, b10, bufB);

  // Fused L5+L6: bufB(32^3,128) -> out(64^3,3)   [R7 proven]
  {
    dim3 g(512, 1, 8);
    fused56b<<<g, 256>>>(bufB, out);
  }
  // Exact boundary fix, warp-per-voxel   [NEW]
  fix56w<<<3072, 256>>>(bufB, b20, out);
}

// round 9
// speedup vs baseline: 2.8296x; 1.4121x over previous
#include <cuda_runtime.h>
#include <cuda_bf16.h>
#include <cstdint>

// ---------------------------------------------------------------------------
// Static scratch (no allocation allowed)
// ---------------------------------------------------------------------------
__device__ float g_bufA[16777216];
__device__ float g_bufB[4194304];
__device__ float g_Wp[279936];      // [k1lin 27][k2lin 27][ci 128][co 3]
__device__ float g_WpT[279936];     // [k1lin 27][k2lin 27][co 3][ci 128]
__device__ float g_Weff[110592];    // [pz 8][dxlin 27][co 3][ci 128]
__device__ float g_bconv[81];       // [k2lin 27][co 3]
__device__ float g_btot[3];
__device__ __nv_bfloat16 g_xhi[4194304];
__device__ __nv_bfloat16 g_xlo[4194304];
__device__ __nv_bfloat16 g_whi[442368];
__device__ __nv_bfloat16 g_wlo[442368];

typedef unsigned long long ull;

// ---------------------------------------------------------------------------
// f32x2 packed helpers
// ---------------------------------------------------------------------------
__device__ __forceinline__ ull pack2(float x, float y){
  ull r; asm("mov.b64 %0, {%1, %2};" : "=l"(r) : "f"(x), "f"(y)); return r;
}
__device__ __forceinline__ void unpack2(ull v, float& x, float& y){
  asm("mov.b64 {%0, %1}, %2;" : "=f"(x), "=f"(y) : "l"(v));
}
__device__ __forceinline__ void ffma2(ull& acc, ull a, ull b){
  asm("fma.rn.f32x2 %0, %1, %2, %0;" : "+l"(acc) : "l"(a), "l"(b));
}

// ---------------------------------------------------------------------------
// mma.sync / ldmatrix helpers (baseline PTX, legal on target sm_103)
// ---------------------------------------------------------------------------
__device__ __forceinline__ void ldsm4(uint32_t* r, const void* p){
  uint32_t a = (uint32_t)__cvta_generic_to_shared(p);
  asm volatile("ldmatrix.sync.aligned.m8n8.x4.shared.b16 {%0,%1,%2,%3}, [%4];"
    : "=r"(r[0]), "=r"(r[1]), "=r"(r[2]), "=r"(r[3]) : "r"(a));
}
__device__ __forceinline__ void ldsm4t(uint32_t* r, const void* p){
  uint32_t a = (uint32_t)__cvta_generic_to_shared(p);
  asm volatile("ldmatrix.sync.aligned.m8n8.x4.trans.shared.b16 {%0,%1,%2,%3}, [%4];"
    : "=r"(r[0]), "=r"(r[1]), "=r"(r[2]), "=r"(r[3]) : "r"(a));
}
__device__ __forceinline__ void mma_bf16(float* c, const uint32_t* a,
                                         uint32_t b0, uint32_t b1){
  asm volatile("mma.sync.aligned.m16n8k16.row.col.f32.bf16.bf16.f32 "
    "{%0,%1,%2,%3}, {%4,%5,%6,%7}, {%8,%9}, {%0,%1,%2,%3};"
    : "+f"(c[0]), "+f"(c[1]), "+f"(c[2]), "+f"(c[3])
    : "r"(a[0]), "r"(a[1]), "r"(a[2]), "r"(a[3]), "r"(b0), "r"(b1));
}

// ---------------------------------------------------------------------------
// ROUND-1 PROVEN KERNEL (verbatim): generic transposed-conv implicit GEMM.
// ---------------------------------------------------------------------------
template<int BM, int TM>
__global__ __launch_bounds__(256) void deconv_gemm(
    const float* __restrict__ x, const float* __restrict__ w,
    const float* __restrict__ bias, float* __restrict__ out,
    int inD, int inH, int inW, int Cin,
    int outD, int outH, int outW, int Cout,
    int stride, int relu)
{
  constexpr int BN = 64;
  constexpr int BK = 16;
  constexpr int NP = TM / 2;

  __shared__ float As[BK][BM];
  __shared__ float Bs[BK][BN];
  __shared__ int   offs[BM];

  const int tid = threadIdx.x;
  const int pz = blockIdx.z;
  const int pd = (pz >> 2) & 1, ph = (pz >> 1) & 1, pw = pz & 1;
  const int rH = outH / stride, rW = outW / stride;
  const int nb = blockIdx.y * BN;
  const int vbase = blockIdx.x * BM;

  int md = 0, mh = 0, mw = 0;
  if (tid < BM) {
    int rv = vbase + tid;
    mw = rv % rW; int t = rv / rW; mh = t % rH; md = t / rH;
  }

  int nkd, kdL[3], ddL[3];
  int nkh, khL[3], dhL[3];
  int nkw, kwL[3], dwL[3];
  auto mk = [&](int p, int& n, int* kL, int* dL){
    if (stride == 1){ n = 3; kL[0]=0; kL[1]=1; kL[2]=2; dL[0]=-1; dL[1]=0; dL[2]=1; }
    else if (p == 0){ n = 2; kL[0]=0; kL[1]=2; dL[0]=-1; dL[1]=0; }
    else            { n = 1; kL[0]=1; dL[0]=0; }
  };
  mk(pd, nkd, kdL, ddL);
  mk(ph, nkh, khL, dhL);
  mk(pw, nkw, kwL, dwL);

  const int mg = tid >> 4, ng = tid & 15;
  const int m0 = mg * TM, n0 = ng * 4;

  ull acc[NP][4];
  #pragma unroll
  for (int i = 0; i < NP; i++)
    #pragma unroll
    for (int j = 0; j < 4; j++) acc[i][j] = 0ull;

  for (int ia = 0; ia < nkd; ia++)
  for (int ib = 0; ib < nkh; ib++)
  for (int ic = 0; ic < nkw; ic++){
    const int tap = (kdL[ia]*3 + khL[ib])*3 + kwL[ic];
    const float* wt = w + (size_t)tap * Cin * Cout + nb;

    __syncthreads();
    if (tid < BM){
      int id = md + ddL[ia];
      int ih = mh + dhL[ib];
      int iw = mw + dwL[ic];
      bool v = (unsigned)id < (unsigned)inD &&
               (unsigned)ih < (unsigned)inH &&
               (unsigned)iw < (unsigned)inW;
      offs[tid] = v ? ((id*inH + ih)*inW + iw) * Cin : -1;
    }

    for (int c0 = 0; c0 < Cin; c0 += BK){
      __syncthreads();
      for (int idx = tid; idx < BM*4; idx += 256){
        int v = idx >> 2, c4 = (idx & 3) * 4;
        int o = offs[v];
        float4 val = make_float4(0.f, 0.f, 0.f, 0.f);
        if (o >= 0) val = *(const float4*)(x + o + c0 + c4);
        As[c4+0][v] = val.x; As[c4+1][v] = val.y;
        As[c4+2][v] = val.z; As[c4+3][v] = val.w;
      }
      {
        int r = tid >> 4, col = (tid & 15) * 4;
        float4 bv = *(const float4*)(wt + (size_t)(c0 + r) * Cout + col);
        *(float4*)&Bs[r][col] = bv;
      }
      __syncthreads();
      #pragma unroll
      for (int kk = 0; kk < BK; kk++){
        const ull* a64 = (const ull*)&As[kk][m0];
        float4 bv = *(const float4*)&Bs[kk][n0];
        ull bp0 = pack2(bv.x, bv.x);
        ull bp1 = pack2(bv.y, bv.y);
        ull bp2 = pack2(bv.z, bv.z);
        ull bp3 = pack2(bv.w, bv.w);
        #pragma unroll
        for (int i = 0; i < NP; i++){
          ull av = a64[i];
          ffma2(acc[i][0], av, bp0);
          ffma2(acc[i][1], av, bp1);
          ffma2(acc[i][2], av, bp2);
          ffma2(acc[i][3], av, bp3);
        }
      }
    }
  }

  float4 b4 = *(const float4*)&bias[nb + n0];
  #pragma unroll
  for (int i = 0; i < NP; i++){
    float r0[4], r1[4];
    #pragma unroll
    for (int j = 0; j < 4; j++) unpack2(acc[i][j], r0[j], r1[j]);
    #pragma unroll
    for (int h = 0; h < 2; h++){
      float* rr = h ? r1 : r0;
      int rv = vbase + m0 + 2*i + h;
      int vw = rv % rW; int t = rv / rW; int vh = t % rH; int vd = t / rH;
      int od = vd*stride + pd, oh = vh*stride + ph, ow = vw*stride + pw;
      size_t oo = (size_t)((od*outH + oh)*outW + ow) * Cout + nb + n0;
      float4 res;
      res.x = rr[0] + b4.x; res.y = rr[1] + b4.y;
      res.z = rr[2] + b4.z; res.w = rr[3] + b4.w;
      if (relu){
        res.x = fmaxf(res.x, 0.f); res.y = fmaxf(res.y, 0.f);
        res.z = fmaxf(res.z, 0.f); res.w = fmaxf(res.w, 0.f);
      }
      *(float4*)&out[oo] = res;
    }
  }
}

// ---------------------------------------------------------------------------
// NEW (round 9): bf16 hi/lo split pre-passes for the HMMA L4 path.
// ---------------------------------------------------------------------------
__global__ __launch_bounds__(256) void split_x_kernel(
    const float* __restrict__ x, __nv_bfloat16* __restrict__ hi,
    __nv_bfloat16* __restrict__ lo, int n4)
{
  int i = blockIdx.x * 256 + threadIdx.x;
  if (i >= n4) return;
  float4 v = ((const float4*)x)[i];
  __nv_bfloat16 h0 = __float2bfloat16_rn(v.x);
  __nv_bfloat16 h1 = __float2bfloat16_rn(v.y);
  __nv_bfloat16 h2 = __float2bfloat16_rn(v.z);
  __nv_bfloat16 h3 = __float2bfloat16_rn(v.w);
  __nv_bfloat16 l0 = __float2bfloat16_rn(v.x - __bfloat162float(h0));
  __nv_bfloat16 l1 = __float2bfloat16_rn(v.y - __bfloat162float(h1));
  __nv_bfloat16 l2 = __float2bfloat16_rn(v.z - __bfloat162float(h2));
  __nv_bfloat16 l3 = __float2bfloat16_rn(v.w - __bfloat162float(h3));
  ushort4 hv = make_ushort4(*(unsigned short*)&h0, *(unsigned short*)&h1,
                            *(unsigned short*)&h2, *(unsigned short*)&h3);
  ushort4 lv = make_ushort4(*(unsigned short*)&l0, *(unsigned short*)&l1,
                            *(unsigned short*)&l2, *(unsigned short*)&l3);
  ((ushort4*)hi)[i] = hv;
  ((ushort4*)lo)[i] = lv;
}

__global__ __launch_bounds__(256) void split_w_kernel(
    const float* __restrict__ w, __nv_bfloat16* __restrict__ hi,
    __nv_bfloat16* __restrict__ lo)
{
  int i = blockIdx.x * 256 + threadIdx.x;
  if (i >= 27*128*128) return;
  float v = w[i];
  __nv_bfloat16 h = __float2bfloat16_rn(v);
  hi[i] = h;
  lo[i] = __float2bfloat16_rn(v - __bfloat162float(h));
}

// ---------------------------------------------------------------------------
// NEW (round 9): L4 on HMMA (mma.sync bf16, 3-pass hi/lo split).
// Stride-1 deconv, DIM=32, C=128, ReLU. Gather structure = R3-proven.
// 8 warps: 2(M) x 4(N); warp tile 64x32; 4x4 m16n8k16 frags, f32 acc.
// A pitch 80B, B pitch 272B: ldmatrix-conflict-free.
// ---------------------------------------------------------------------------
__global__ __launch_bounds__(256, 2) void mma_s1r(
    const __nv_bfloat16* __restrict__ xhi, const __nv_bfloat16* __restrict__ xlo,
    const __nv_bfloat16* __restrict__ whi, const __nv_bfloat16* __restrict__ wlo,
    const float* __restrict__ bias, float* __restrict__ out)
{
  constexpr int BM = 128, BK = 32;
  constexpr int AP = 40;    // A row pitch in bf16 (80B)
  constexpr int BP = 136;   // B row pitch in bf16 (272B)

  __shared__ __align__(16) unsigned short Ahi[BM*AP];
  __shared__ __align__(16) unsigned short Alo[BM*AP];
  __shared__ __align__(16) unsigned short Bhi[BK*BP];
  __shared__ __align__(16) unsigned short Blo[BK*BP];
  __shared__ int offs[BM];

  const int tid  = threadIdx.x;
  const int lane = tid & 31;
  const int wid  = tid >> 5;
  const int warp_m = wid >> 2;      // 0..1
  const int warp_n = wid & 3;       // 0..3
  const int vbase = blockIdx.x * BM;

  // voxel coords for offs (tid < 128)
  int md, mh, mw;
  { int rv = vbase + (tid & 127);
    mw = rv & 31; int t = rv >> 5; mh = t & 31; md = t >> 5; }

  // ldmatrix per-thread address components
  const int a_row_in = lane & 15;
  const int a_colb   = (lane >> 4) << 3;
  const int b_krow   = lane & 15;
  const int b_coln   = (lane >> 4) << 3;

  float acc[4][4][4];
  #pragma unroll
  for (int mi = 0; mi < 4; mi++)
    #pragma unroll
    for (int ni = 0; ni < 4; ni++)
      #pragma unroll
      for (int q = 0; q < 4; q++) acc[mi][ni][q] = 0.f;

  for (int tap = 0; tap < 27; tap++){
    const int kw = tap % 3, kh = (tap / 3) % 3, kd = tap / 9;
    __syncthreads();
    if (tid < BM){
      int id = md + kd - 1, ih = mh + kh - 1, iw = mw + kw - 1;
      bool v = (unsigned)id < 32u && (unsigned)ih < 32u && (unsigned)iw < 32u;
      offs[tid] = v ? ((id*32 + ih)*32 + iw) * 128 : -1;
    }

    for (int c0 = 0; c0 < 128; c0 += BK){
      __syncthreads();
      // ---- A fill (gather, hi+lo): 128 rows x 32 bf16 ----
      #pragma unroll
      for (int rep = 0; rep < 2; rep++){
        int idx = rep * 256 + tid;
        int row = idx >> 2, cg = idx & 3;
        int o = offs[row];
        uint4 h = make_uint4(0,0,0,0), l = make_uint4(0,0,0,0);
        if (o >= 0){
          h = *(const uint4*)(xhi + o + c0 + cg*8);
          l = *(const uint4*)(xlo + o + c0 + cg*8);
        }
        *(uint4*)&Ahi[row*AP + cg*8] = h;
        *(uint4*)&Alo[row*AP + cg*8] = l;
      }
      // ---- B fill: 32 k-rows x 128 couts ----
      #pragma unroll
      for (int rep = 0; rep < 2; rep++){
        int idx = rep * 256 + tid;
        int kr = idx >> 4, cg = idx & 15;
        int src = tap*16384 + (c0 + kr)*128 + cg*8;
        *(uint4*)&Bhi[kr*BP + cg*8] = *(const uint4*)(whi + src);
        *(uint4*)&Blo[kr*BP + cg*8] = *(const uint4*)(wlo + src);
      }
      __syncthreads();

      #pragma unroll
      for (int k16 = 0; k16 < 2; k16++){
        uint32_t af[4][4], bh[2][4], bl[2][4];
        // A-hi frags
        #pragma unroll
        for (int mi = 0; mi < 4; mi++){
          int r = warp_m*64 + mi*16 + a_row_in;
          ldsm4(af[mi], &Ahi[r*AP + k16*16 + a_colb]);
        }
        // B-hi / B-lo frags
        #pragma unroll
        for (int nj = 0; nj < 2; nj++){
          int kr = k16*16 + b_krow;
          int nc = warp_n*32 + nj*16 + b_coln;
          ldsm4t(bh[nj], &Bhi[kr*BP + nc]);
          ldsm4t(bl[nj], &Blo[kr*BP + nc]);
        }
        // pass 1: Ahi x Bhi ; pass 2: Ahi x Blo
        #pragma unroll
        for (int mi = 0; mi < 4; mi++)
          #pragma unroll
          for (int ni = 0; ni < 4; ni++){
            const uint32_t* h = &bh[ni>>1][(ni&1)*2];
            const uint32_t* L = &bl[ni>>1][(ni&1)*2];
            mma_bf16(acc[mi][ni], af[mi], h[0], h[1]);
            mma_bf16(acc[mi][ni], af[mi], L[0], L[1]);
          }
        // pass 3: Alo x Bhi (reuse af regs)
        #pragma unroll
        for (int mi = 0; mi < 4; mi++){
          int r = warp_m*64 + mi*16 + a_row_in;
          ldsm4(af[mi], &Alo[r*AP + k16*16 + a_colb]);
        }
        #pragma unroll
        for (int mi = 0; mi < 4; mi++)
          #pragma unroll
          for (int ni = 0; ni < 4; ni++){
            const uint32_t* h = &bh[ni>>1][(ni&1)*2];
            mma_bf16(acc[mi][ni], af[mi], h[0], h[1]);
          }
      }
    }
  }

  // ---- epilogue: bias + relu, linear stores ----
  #pragma unroll
  for (int mi = 0; mi < 4; mi++){
    int v0 = vbase + warp_m*64 + mi*16 + (lane >> 2);
    #pragma unroll
    for (int ni = 0; ni < 4; ni++){
      int col = warp_n*32 + ni*8 + (lane & 3)*2;
      float2 bb = *(const float2*)&bias[col];
      float2 r0, r1;
      r0.x = fmaxf(acc[mi][ni][0] + bb.x, 0.f);
      r0.y = fmaxf(acc[mi][ni][1] + bb.y, 0.f);
      r1.x = fmaxf(acc[mi][ni][2] + bb.x, 0.f);
      r1.y = fmaxf(acc[mi][ni][3] + bb.y, 0.f);
      *(float2*)&out[(size_t)v0*128 + col]     = r0;
      *(float2*)&out[(size_t)(v0+8)*128 + col] = r1;
    }
  }
}

// ---------------------------------------------------------------------------
// Fused L5+L6 path tables (R6-proven).
// ---------------------------------------------------------------------------
__device__ __constant__ int c_np[2][3]   = {{2,2,0},{1,3,1}};
__device__ __constant__ int c_k1[2][3][3] = {{{1,0,0},{2,1,0},{0,0,0}},
                                             {{0,0,0},{2,1,0},{2,0,0}}};
__device__ __constant__ int c_k2[2][3][3] = {{{0,1,0},{1,2,0},{0,0,0}},
                                             {{0,0,0},{0,1,2},{2,0,0}}};

// P1 (R6-proven, verbatim): Wp[k1][k2][ci][co]
__global__ __launch_bounds__(256) void p1_wp(
    const float* __restrict__ w2, const float* __restrict__ w20)
{
  int t = blockIdx.x * 256 + threadIdx.x;
  if (t >= 27*27*128) return;
  int ci = t & 127;
  int k2l = (t >> 7) % 27;
  int k1l = t / (27*128);
  const float* a = w2 + ((size_t)k1l*128 + ci) * 64;
  const float* b = w20 + (size_t)k2l * 64 * 3;
  float s0 = 0.f, s1 = 0.f, s2 = 0.f;
  #pragma unroll 4
  for (int cm = 0; cm < 64; cm++){
    float av = a[cm];
    s0 = fmaf(av, b[cm*3+0], s0);
    s1 = fmaf(av, b[cm*3+1], s1);
    s2 = fmaf(av, b[cm*3+2], s2);
  }
  float* o = g_Wp + (size_t)t * 3;
  o[0] = s0; o[1] = s1; o[2] = s2;
}

// R8-proven: transpose Wp -> WpT[k1,k2][co][ci]
__global__ __launch_bounds__(256) void p1t_wpT()
{
  int t = blockIdx.x * 256 + threadIdx.x;
  if (t >= 279936) return;
  int ci = t & 127;
  int co = (t >> 7) % 3;
  int kk = t / 384;
  g_WpT[(size_t)kk*384 + co*128 + ci] = g_Wp[((size_t)kk*128 + ci)*3 + co];
}

// P2 (R7-proven, verbatim): Weff[pz][dxl][co][ci]
__global__ __launch_bounds__(256) void p2_weff()
{
  int t = blockIdx.x * 256 + threadIdx.x;
  if (t >= 8*27*128) return;
  int ci = t & 127;
  int dxl = (t >> 7) % 27;
  int pz = t / (27*128);
  int jd = dxl / 9, jh = (dxl / 3) % 3, jw = dxl % 3;
  int pd = (pz >> 2) & 1, ph = (pz >> 1) & 1, pw = pz & 1;
  int nd = c_np[pd][jd], nh = c_np[ph][jh], nw = c_np[pw][jw];
  float s0 = 0.f, s1 = 0.f, s2 = 0.f;
  for (int a = 0; a < nd; a++)
  for (int b = 0; b < nh; b++)
  for (int c = 0; c < nw; c++){
    int k1l = (c_k1[pd][jd][a]*3 + c_k1[ph][jh][b])*3 + c_k1[pw][jw][c];
    int k2l = (c_k2[pd][jd][a]*3 + c_k2[ph][jh][b])*3 + c_k2[pw][jw][c];
    const float* wp = g_Wp + ((size_t)(k1l*27 + k2l)*128 + ci)*3;
    s0 += wp[0]; s1 += wp[1]; s2 += wp[2];
  }
  float* o = g_Weff + (size_t)(pz*27 + dxl) * 3 * 128;
  o[0*128 + ci] = s0;
  o[1*128 + ci] = s1;
  o[2*128 + ci] = s2;
}

// P3 (R6-proven, verbatim)
__global__ void p3_bias(const float* __restrict__ w20,
                        const float* __restrict__ b2,
                        const float* __restrict__ b20)
{
  int tid = threadIdx.x;
  if (tid < 81){
    int k2 = tid / 3, co = tid % 3;
    float s = 0.f;
    for (int cm = 0; cm < 64; cm++)
      s = fmaf(w20[(k2*64+cm)*3+co], b2[cm], s);
    g_bconv[tid] = s;
  }
  __syncthreads();
  if (tid < 3){
    float s = b20[tid];
    for (int k2 = 0; k2 < 27; k2++) s += g_bconv[k2*3+tid];
    g_btot[tid] = s;
  }
}

// ---------------------------------------------------------------------------
// Fused L5+L6 consumer (R7-proven, verbatim).
// ---------------------------------------------------------------------------
__global__ __launch_bounds__(256) void fused56b(
    const float* __restrict__ x, float* __restrict__ out)
{
  const int wid  = threadIdx.x >> 5;
  const int lane = threadIdx.x & 31;
  const int pz = blockIdx.z;
  const int pd = (pz >> 2) & 1, ph = (pz >> 1) & 1, pw = pz & 1;
  const int wg  = blockIdx.x * 8 + wid;
  const int seg = wg & 3;
  const int row = wg >> 2;
  const int rd = row >> 5, rh = row & 31;
  const int rw0 = seg * 8;
  const int l2 = 2 * lane;

  ull acc[8][3];
  #pragma unroll
  for (int r = 0; r < 8; r++)
    #pragma unroll
    for (int c = 0; c < 3; c++) acc[r][c] = 0ull;

  for (int jd = 0; jd <= 1 + pd; jd++){
    int id = rd + jd - 1;
    if ((unsigned)id >= 32u) continue;
    for (int jh = 0; jh <= 1 + ph; jh++){
      int ih = rh + jh - 1;
      if ((unsigned)ih >= 32u) continue;
      const float* xrow = x + (size_t)((id*32 + ih)*32) * 128;
      for (int jw = 0; jw <= 1 + pw; jw++){
        const int dxl = jd*9 + jh*3 + jw;
        const float* Wt = g_Weff + (size_t)(pz*27 + dxl) * 3 * 128;
        ull w00 = *(const ull*)(Wt +   0 + l2);
        ull w01 = *(const ull*)(Wt +  64 + l2);
        ull w10 = *(const ull*)(Wt + 128 + l2);
        ull w11 = *(const ull*)(Wt + 192 + l2);
        ull w20 = *(const ull*)(Wt + 256 + l2);
        ull w21 = *(const ull*)(Wt + 320 + l2);
        #pragma unroll
        for (int r = 0; r < 8; r++){
          int iw = rw0 + r + jw - 1;
          if ((unsigned)iw < 32u){
            const float* xp = xrow + iw * 128;
            ull x0 = *(const ull*)(xp + l2);
            ull x1 = *(const ull*)(xp + 64 + l2);
            ffma2(acc[r][0], x0, w00); ffma2(acc[r][0], x1, w01);
            ffma2(acc[r][1], x0, w10); ffma2(acc[r][1], x1, w11);
            ffma2(acc[r][2], x0, w20); ffma2(acc[r][2], x1, w21);
          }
        }
      }
    }
  }

  const float bt0 = g_btot[0], bt1 = g_btot[1], bt2 = g_btot[2];
  const int od = 2*rd + pd, oh = 2*rh + ph;

  #pragma unroll
  for (int r = 0; r < 8; r++){
    float s0, s1, s2;
    {
      float a, b;
      unpack2(acc[r][0], a, b); s0 = a + b;
      unpack2(acc[r][1], a, b); s1 = a + b;
      unpack2(acc[r][2], a, b); s2 = a + b;
    }
    #pragma unroll
    for (int sh = 16; sh > 0; sh >>= 1){
      s0 += __shfl_xor_sync(0xffffffffu, s0, sh);
      s1 += __shfl_xor_sync(0xffffffffu, s1, sh);
      s2 += __shfl_xor_sync(0xffffffffu, s2, sh);
    }
    if (lane == 0){
      int ow = 2*(rw0 + r) + pw;
      float* op = out + (size_t)((od*64 + oh)*64 + ow) * 3;
      op[0] = s0 + bt0;
      op[1] = s1 + bt1;
      op[2] = s2 + bt2;
    }
  }
}

// ---------------------------------------------------------------------------
// fix56w (R8-proven, verbatim): warp-per-voxel exact boundary fix.
// ---------------------------------------------------------------------------
__global__ __launch_bounds__(256) void fix56w(
    const float* __restrict__ x, const float* __restrict__ b20,
    float* __restrict__ out)
{
  const int gw = blockIdx.x * 8 + (threadIdx.x >> 5);
  const int lane = threadIdx.x & 31;
  const int l2 = 2 * lane;

  int plane = gw / 4096, r = gw % 4096;
  int a = r / 64, b = r % 64;
  int od, oh, ow;
  if      (plane == 0){ od = 0;  oh = a; ow = b; }
  else if (plane == 1){ od = 63; oh = a; ow = b; }
  else if (plane == 2){ oh = 0;  od = a; ow = b; if (od==0||od==63) return; }
  else if (plane == 3){ oh = 63; od = a; ow = b; if (od==0||od==63) return; }
  else if (plane == 4){ ow = 0;  od = a; oh = b; if (od==0||od==63||oh==0||oh==63) return; }
  else               { ow = 63; od = a; oh = b; if (od==0||od==63||oh==0||oh==63) return; }

  ull a0 = 0ull, a1 = 0ull, a2 = 0ull;
  float bias0 = __ldg(&b20[0]), bias1 = __ldg(&b20[1]), bias2 = __ldg(&b20[2]);

  for (int k2d = 0; k2d < 3; k2d++){
    int md = od + k2d - 1; if ((unsigned)md >= 64u) continue;
    int pmd = md & 1, rd = (md - pmd) >> 1;
    int n_d = pmd ? 1 : 2;
    int k1d[2], ixd[2];
    if (pmd){ k1d[0] = 1; ixd[0] = rd; }
    else    { k1d[0] = 0; ixd[0] = rd - 1; k1d[1] = 2; ixd[1] = rd; }
    for (int k2h = 0; k2h < 3; k2h++){
      int mh = oh + k2h - 1; if ((unsigned)mh >= 64u) continue;
      int pmh = mh & 1, rh = (mh - pmh) >> 1;
      int n_h = pmh ? 1 : 2;
      int k1h[2], ixh[2];
      if (pmh){ k1h[0] = 1; ixh[0] = rh; }
      else    { k1h[0] = 0; ixh[0] = rh - 1; k1h[1] = 2; ixh[1] = rh; }
      for (int k2w = 0; k2w < 3; k2w++){
        int mw = ow + k2w - 1; if ((unsigned)mw >= 64u) continue;
        int pmw = mw & 1, rw = (mw - pmw) >> 1;
        int n_w = pmw ? 1 : 2;
        int k1w[2], ixw[2];
        if (pmw){ k1w[0] = 1; ixw[0] = rw; }
        else    { k1w[0] = 0; ixw[0] = rw - 1; k1w[1] = 2; ixw[1] = rw; }

        int k2l = (k2d*3 + k2h)*3 + k2w;
        bias0 += g_bconv[k2l*3+0];
        bias1 += g_bconv[k2l*3+1];
        bias2 += g_bconv[k2l*3+2];

        for (int ia = 0; ia < n_d; ia++){
          if ((unsigned)ixd[ia] >= 32u) continue;
          for (int ib = 0; ib < n_h; ib++){
            if ((unsigned)ixh[ib] >= 32u) continue;
            for (int ic = 0; ic < n_w; ic++){
              if ((unsigned)ixw[ic] >= 32u) continue;
              int k1l = (k1d[ia]*3 + k1h[ib])*3 + k1w[ic];
              const float* wt = g_WpT + (size_t)(k1l*27 + k2l)*384;
              const float* xp = x + (size_t)((ixd[ia]*32 + ixh[ib])*32 + ixw[ic])*128;
              ull x0 = *(const ull*)(xp + l2);
              ull x1 = *(const ull*)(xp + 64 + l2);
              ffma2(a0, x0, *(const ull*)(wt +   0 + l2));
              ffma2(a0, x1, *(const ull*)(wt +  64 + l2));
              ffma2(a1, x0, *(const ull*)(wt + 128 + l2));
              ffma2(a1, x1, *(const ull*)(wt + 192 + l2));
              ffma2(a2, x0, *(const ull*)(wt + 256 + l2));
              ffma2(a2, x1, *(const ull*)(wt + 320 + l2));
            }
          }
        }
      }
    }
  }

  float s0, s1, s2;
  {
    float u, v;
    unpack2(a0, u, v); s0 = u + v;
    unpack2(a1, u, v); s1 = u + v;
    unpack2(a2, u, v); s2 = u + v;
  }
  #pragma unroll
  for (int sh = 16; sh > 0; sh >>= 1){
    s0 += __shfl_xor_sync(0xffffffffu, s0, sh);
    s1 += __shfl_xor_sync(0xffffffffu, s1, sh);
    s2 += __shfl_xor_sync(0xffffffffu, s2, sh);
  }
  if (lane == 0){
    float* op = out + (size_t)((od*64 + oh)*64 + ow) * 3;
    op[0] = s0 + bias0;
    op[1] = s1 + bias1;
    op[2] = s2 + bias2;
  }
}

// ---------------------------------------------------------------------------
// kernel_launch
// ---------------------------------------------------------------------------
extern "C" void kernel_launch(void* const* d_in, const int* in_sizes, int n_in,
                              void* d_out, int out_size)
{
  (void)in_sizes; (void)n_in; (void)out_size;
  const float* x   = (const float*)d_in[0];
  const float* w0  = (const float*)d_in[1];
  const float* b0  = (const float*)d_in[2];
  const float* w00 = (const float*)d_in[3];
  const float* b00 = (const float*)d_in[4];
  const float* w1  = (const float*)d_in[5];
  const float* b1  = (const float*)d_in[6];
  const float* w10 = (const float*)d_in[7];
  const float* b10 = (const float*)d_in[8];
  const float* w2  = (const float*)d_in[9];
  const float* b2  = (const float*)d_in[10];
  const float* w20 = (const float*)d_in[11];
  const float* b20 = (const float*)d_in[12];
  float* out = (float*)d_out;

  float *bufA = nullptr, *bufB = nullptr;
  __nv_bfloat16 *xhi = nullptr, *xlo = nullptr, *whi = nullptr, *wlo = nullptr;
  cudaGetSymbolAddress((void**)&bufA, g_bufA);
  cudaGetSymbolAddress((void**)&bufB, g_bufB);
  cudaGetSymbolAddress((void**)&xhi, g_xhi);
  cudaGetSymbolAddress((void**)&xlo, g_xlo);
  cudaGetSymbolAddress((void**)&whi, g_whi);
  cudaGetSymbolAddress((void**)&wlo, g_wlo);

  // Precompute fused L5+L6 weights + L4 weight split (input-only deps)
  p1_wp<<<(27*27*128 + 255)/256, 256>>>(w2, w20);
  p1t_wpT<<<(279936 + 255)/256, 256>>>();
  p2_weff<<<(8*27*128 + 255)/256, 256>>>();
  p3_bias<<<1, 128>>>(w20, b2, b20);
  split_w_kernel<<<1728, 256>>>(w10, whi, wlo);

  // L1: deconv0 s2: x(8^3,128) -> bufA(16^3,128)   [R1 proven]
  {
    dim3 g(512/32, 128/64, 8);
    deconv_gemm<32,2><<<g, 256>>>(x,  w0,  b0,  bufA,
                                  8,8,8,128,  16,16,16,128, 2, 0);
  }
  // L2: deconv0_0 s1 + relu: bufA -> bufB(16^3,128)   [R1 proven]
  {
    dim3 g(4096/32, 128/64, 1);
    deconv_gemm<32,2><<<g, 256>>>(bufA, w00, b00, bufB,
                                  16,16,16,128, 16,16,16,128, 1, 1);
  }
  // L3: deconv1 s2: bufB -> bufA(32^3,128)   [R1 proven]
  {
    dim3 g(4096/128, 128/64, 8);
    deconv_gemm<128,8><<<g, 256>>>(bufB, w1, b1, bufA,
                                   16,16,16,128, 32,32,32,128, 2, 0);
  }
  // L4 on HMMA: split bufA -> bf16 hi/lo, then mma.sync GEMM  [NEW]
  split_x_kernel<<<4096, 256>>>(bufA, xhi, xlo, 4194304/4);
  mma_s1r<<<256, 256>>>(xhi, xlo, whi, wlo, b10, bufB);

  // Fused L5+L6: bufB(32^3,128) -> out(64^3,3)   [R7 proven]
  {
    dim3 g(512, 1, 8);
    fused56b<<<g, 256>>>(bufB, out);
  }
  // Exact boundary fix, warp-per-voxel   [R8 proven]
  fix56w<<<3072, 256>>>(bufB, b20, out);
}

// round 10
// speedup vs baseline: 2.9779x; 1.0524x over previous
#include <cuda_runtime.h>
#include <cuda_bf16.h>
#include <cstdint>

// ---------------------------------------------------------------------------
// Static scratch (no allocation allowed)
// ---------------------------------------------------------------------------
__device__ float g_bufA[16777216];
__device__ float g_bufB[4194304];
__device__ float g_Wp[279936];      // [k1lin 27][k2lin 27][ci 128][co 3]
__device__ float g_WpT[279936];     // [k1lin 27][k2lin 27][co 3][ci 128]
__device__ float g_Weff[110592];    // [pz 8][dxlin 27][co 3][ci 128]
__device__ float g_bconv[81];       // [k2lin 27][co 3]
__device__ float g_btot[3];
__device__ __nv_bfloat16 g_xhi[4194304];
__device__ __nv_bfloat16 g_xlo[4194304];
__device__ __nv_bfloat16 g_whi[442368];    // L4 weights (w10)
__device__ __nv_bfloat16 g_wlo[442368];
__device__ __nv_bfloat16 g_whiB[442368];   // L3 weights (w1)
__device__ __nv_bfloat16 g_wloB[442368];

typedef unsigned long long ull;

// ---------------------------------------------------------------------------
// f32x2 packed helpers
// ---------------------------------------------------------------------------
__device__ __forceinline__ ull pack2(float x, float y){
  ull r; asm("mov.b64 %0, {%1, %2};" : "=l"(r) : "f"(x), "f"(y)); return r;
}
__device__ __forceinline__ void unpack2(ull v, float& x, float& y){
  asm("mov.b64 {%0, %1}, %2;" : "=f"(x), "=f"(y) : "l"(v));
}
__device__ __forceinline__ void ffma2(ull& acc, ull a, ull b){
  asm("fma.rn.f32x2 %0, %1, %2, %0;" : "+l"(acc) : "l"(a), "l"(b));
}

// ---------------------------------------------------------------------------
// mma.sync / ldmatrix helpers (baseline PTX, legal on target sm_103)
// ---------------------------------------------------------------------------
__device__ __forceinline__ void ldsm4(uint32_t* r, const void* p){
  uint32_t a = (uint32_t)__cvta_generic_to_shared(p);
  asm volatile("ldmatrix.sync.aligned.m8n8.x4.shared.b16 {%0,%1,%2,%3}, [%4];"
    : "=r"(r[0]), "=r"(r[1]), "=r"(r[2]), "=r"(r[3]) : "r"(a));
}
__device__ __forceinline__ void ldsm4t(uint32_t* r, const void* p){
  uint32_t a = (uint32_t)__cvta_generic_to_shared(p);
  asm volatile("ldmatrix.sync.aligned.m8n8.x4.trans.shared.b16 {%0,%1,%2,%3}, [%4];"
    : "=r"(r[0]), "=r"(r[1]), "=r"(r[2]), "=r"(r[3]) : "r"(a));
}
__device__ __forceinline__ void mma_bf16(float* c, const uint32_t* a,
                                         uint32_t b0, uint32_t b1){
  asm volatile("mma.sync.aligned.m16n8k16.row.col.f32.bf16.bf16.f32 "
    "{%0,%1,%2,%3}, {%4,%5,%6,%7}, {%8,%9}, {%0,%1,%2,%3};"
    : "+f"(c[0]), "+f"(c[1]), "+f"(c[2]), "+f"(c[3])
    : "r"(a[0]), "r"(a[1]), "r"(a[2]), "r"(a[3]), "r"(b0), "r"(b1));
}

// ---------------------------------------------------------------------------
// ROUND-1 PROVEN KERNEL (verbatim): generic transposed-conv implicit GEMM.
// ---------------------------------------------------------------------------
template<int BM, int TM>
__global__ __launch_bounds__(256) void deconv_gemm(
    const float* __restrict__ x, const float* __restrict__ w,
    const float* __restrict__ bias, float* __restrict__ out,
    int inD, int inH, int inW, int Cin,
    int outD, int outH, int outW, int Cout,
    int stride, int relu)
{
  constexpr int BN = 64;
  constexpr int BK = 16;
  constexpr int NP = TM / 2;

  __shared__ float As[BK][BM];
  __shared__ float Bs[BK][BN];
  __shared__ int   offs[BM];

  const int tid = threadIdx.x;
  const int pz = blockIdx.z;
  const int pd = (pz >> 2) & 1, ph = (pz >> 1) & 1, pw = pz & 1;
  const int rH = outH / stride, rW = outW / stride;
  const int nb = blockIdx.y * BN;
  const int vbase = blockIdx.x * BM;

  int md = 0, mh = 0, mw = 0;
  if (tid < BM) {
    int rv = vbase + tid;
    mw = rv % rW; int t = rv / rW; mh = t % rH; md = t / rH;
  }

  int nkd, kdL[3], ddL[3];
  int nkh, khL[3], dhL[3];
  int nkw, kwL[3], dwL[3];
  auto mk = [&](int p, int& n, int* kL, int* dL){
    if (stride == 1){ n = 3; kL[0]=0; kL[1]=1; kL[2]=2; dL[0]=-1; dL[1]=0; dL[2]=1; }
    else if (p == 0){ n = 2; kL[0]=0; kL[1]=2; dL[0]=-1; dL[1]=0; }
    else            { n = 1; kL[0]=1; dL[0]=0; }
  };
  mk(pd, nkd, kdL, ddL);
  mk(ph, nkh, khL, dhL);
  mk(pw, nkw, kwL, dwL);

  const int mg = tid >> 4, ng = tid & 15;
  const int m0 = mg * TM, n0 = ng * 4;

  ull acc[NP][4];
  #pragma unroll
  for (int i = 0; i < NP; i++)
    #pragma unroll
    for (int j = 0; j < 4; j++) acc[i][j] = 0ull;

  for (int ia = 0; ia < nkd; ia++)
  for (int ib = 0; ib < nkh; ib++)
  for (int ic = 0; ic < nkw; ic++){
    const int tap = (kdL[ia]*3 + khL[ib])*3 + kwL[ic];
    const float* wt = w + (size_t)tap * Cin * Cout + nb;

    __syncthreads();
    if (tid < BM){
      int id = md + ddL[ia];
      int ih = mh + dhL[ib];
      int iw = mw + dwL[ic];
      bool v = (unsigned)id < (unsigned)inD &&
               (unsigned)ih < (unsigned)inH &&
               (unsigned)iw < (unsigned)inW;
      offs[tid] = v ? ((id*inH + ih)*inW + iw) * Cin : -1;
    }

    for (int c0 = 0; c0 < Cin; c0 += BK){
      __syncthreads();
      for (int idx = tid; idx < BM*4; idx += 256){
        int v = idx >> 2, c4 = (idx & 3) * 4;
        int o = offs[v];
        float4 val = make_float4(0.f, 0.f, 0.f, 0.f);
        if (o >= 0) val = *(const float4*)(x + o + c0 + c4);
        As[c4+0][v] = val.x; As[c4+1][v] = val.y;
        As[c4+2][v] = val.z; As[c4+3][v] = val.w;
      }
      {
        int r = tid >> 4, col = (tid & 15) * 4;
        float4 bv = *(const float4*)(wt + (size_t)(c0 + r) * Cout + col);
        *(float4*)&Bs[r][col] = bv;
      }
      __syncthreads();
      #pragma unroll
      for (int kk = 0; kk < BK; kk++){
        const ull* a64 = (const ull*)&As[kk][m0];
        float4 bv = *(const float4*)&Bs[kk][n0];
        ull bp0 = pack2(bv.x, bv.x);
        ull bp1 = pack2(bv.y, bv.y);
        ull bp2 = pack2(bv.z, bv.z);
        ull bp3 = pack2(bv.w, bv.w);
        #pragma unroll
        for (int i = 0; i < NP; i++){
          ull av = a64[i];
          ffma2(acc[i][0], av, bp0);
          ffma2(acc[i][1], av, bp1);
          ffma2(acc[i][2], av, bp2);
          ffma2(acc[i][3], av, bp3);
        }
      }
    }
  }

  float4 b4 = *(const float4*)&bias[nb + n0];
  #pragma unroll
  for (int i = 0; i < NP; i++){
    float r0[4], r1[4];
    #pragma unroll
    for (int j = 0; j < 4; j++) unpack2(acc[i][j], r0[j], r1[j]);
    #pragma unroll
    for (int h = 0; h < 2; h++){
      float* rr = h ? r1 : r0;
      int rv = vbase + m0 + 2*i + h;
      int vw = rv % rW; int t = rv / rW; int vh = t % rH; int vd = t / rH;
      int od = vd*stride + pd, oh = vh*stride + ph, ow = vw*stride + pw;
      size_t oo = (size_t)((od*outH + oh)*outW + ow) * Cout + nb + n0;
      float4 res;
      res.x = rr[0] + b4.x; res.y = rr[1] + b4.y;
      res.z = rr[2] + b4.z; res.w = rr[3] + b4.w;
      if (relu){
        res.x = fmaxf(res.x, 0.f); res.y = fmaxf(res.y, 0.f);
        res.z = fmaxf(res.z, 0.f); res.w = fmaxf(res.w, 0.f);
      }
      *(float4*)&out[oo] = res;
    }
  }
}

// ---------------------------------------------------------------------------
// bf16 hi/lo split pre-passes (R9-proven, verbatim)
// ---------------------------------------------------------------------------
__global__ __launch_bounds__(256) void split_x_kernel(
    const float* __restrict__ x, __nv_bfloat16* __restrict__ hi,
    __nv_bfloat16* __restrict__ lo, int n4)
{
  int i = blockIdx.x * 256 + threadIdx.x;
  if (i >= n4) return;
  float4 v = ((const float4*)x)[i];
  __nv_bfloat16 h0 = __float2bfloat16_rn(v.x);
  __nv_bfloat16 h1 = __float2bfloat16_rn(v.y);
  __nv_bfloat16 h2 = __float2bfloat16_rn(v.z);
  __nv_bfloat16 h3 = __float2bfloat16_rn(v.w);
  __nv_bfloat16 l0 = __float2bfloat16_rn(v.x - __bfloat162float(h0));
  __nv_bfloat16 l1 = __float2bfloat16_rn(v.y - __bfloat162float(h1));
  __nv_bfloat16 l2 = __float2bfloat16_rn(v.z - __bfloat162float(h2));
  __nv_bfloat16 l3 = __float2bfloat16_rn(v.w - __bfloat162float(h3));
  ushort4 hv = make_ushort4(*(unsigned short*)&h0, *(unsigned short*)&h1,
                            *(unsigned short*)&h2, *(unsigned short*)&h3);
  ushort4 lv = make_ushort4(*(unsigned short*)&l0, *(unsigned short*)&l1,
                            *(unsigned short*)&l2, *(unsigned short*)&l3);
  ((ushort4*)hi)[i] = hv;
  ((ushort4*)lo)[i] = lv;
}

__global__ __launch_bounds__(256) void split_w_kernel(
    const float* __restrict__ w, __nv_bfloat16* __restrict__ hi,
    __nv_bfloat16* __restrict__ lo)
{
  int i = blockIdx.x * 256 + threadIdx.x;
  if (i >= 27*128*128) return;
  float v = w[i];
  __nv_bfloat16 h = __float2bfloat16_rn(v);
  hi[i] = h;
  lo[i] = __float2bfloat16_rn(v - __bfloat162float(h));
}

// ---------------------------------------------------------------------------
// R9-PROVEN: L4 on HMMA (mma.sync bf16, 3-pass hi/lo split). Verbatim.
// ---------------------------------------------------------------------------
__global__ __launch_bounds__(256, 2) void mma_s1r(
    const __nv_bfloat16* __restrict__ xhi, const __nv_bfloat16* __restrict__ xlo,
    const __nv_bfloat16* __restrict__ whi, const __nv_bfloat16* __restrict__ wlo,
    const float* __restrict__ bias, float* __restrict__ out)
{
  constexpr int BM = 128, BK = 32;
  constexpr int AP = 40;
  constexpr int BP = 136;

  __shared__ __align__(16) unsigned short Ahi[BM*AP];
  __shared__ __align__(16) unsigned short Alo[BM*AP];
  __shared__ __align__(16) unsigned short Bhi[BK*BP];
  __shared__ __align__(16) unsigned short Blo[BK*BP];
  __shared__ int offs[BM];

  const int tid  = threadIdx.x;
  const int lane = tid & 31;
  const int wid  = tid >> 5;
  const int warp_m = wid >> 2;
  const int warp_n = wid & 3;
  const int vbase = blockIdx.x * BM;

  int md, mh, mw;
  { int rv = vbase + (tid & 127);
    mw = rv & 31; int t = rv >> 5; mh = t & 31; md = t >> 5; }

  const int a_row_in = lane & 15;
  const int a_colb   = (lane >> 4) << 3;
  const int b_krow   = lane & 15;
  const int b_coln   = (lane >> 4) << 3;

  float acc[4][4][4];
  #pragma unroll
  for (int mi = 0; mi < 4; mi++)
    #pragma unroll
    for (int ni = 0; ni < 4; ni++)
      #pragma unroll
      for (int q = 0; q < 4; q++) acc[mi][ni][q] = 0.f;

  for (int tap = 0; tap < 27; tap++){
    const int kw = tap % 3, kh = (tap / 3) % 3, kd = tap / 9;
    __syncthreads();
    if (tid < BM){
      int id = md + kd - 1, ih = mh + kh - 1, iw = mw + kw - 1;
      bool v = (unsigned)id < 32u && (unsigned)ih < 32u && (unsigned)iw < 32u;
      offs[tid] = v ? ((id*32 + ih)*32 + iw) * 128 : -1;
    }

    for (int c0 = 0; c0 < 128; c0 += BK){
      __syncthreads();
      #pragma unroll
      for (int rep = 0; rep < 2; rep++){
        int idx = rep * 256 + tid;
        int row = idx >> 2, cg = idx & 3;
        int o = offs[row];
        uint4 h = make_uint4(0,0,0,0), l = make_uint4(0,0,0,0);
        if (o >= 0){
          h = *(const uint4*)(xhi + o + c0 + cg*8);
          l = *(const uint4*)(xlo + o + c0 + cg*8);
        }
        *(uint4*)&Ahi[row*AP + cg*8] = h;
        *(uint4*)&Alo[row*AP + cg*8] = l;
      }
      #pragma unroll
      for (int rep = 0; rep < 2; rep++){
        int idx = rep * 256 + tid;
        int kr = idx >> 4, cg = idx & 15;
        int src = tap*16384 + (c0 + kr)*128 + cg*8;
        *(uint4*)&Bhi[kr*BP + cg*8] = *(const uint4*)(whi + src);
        *(uint4*)&Blo[kr*BP + cg*8] = *(const uint4*)(wlo + src);
      }
      __syncthreads();

      #pragma unroll
      for (int k16 = 0; k16 < 2; k16++){
        uint32_t af[4][4], bh[2][4], bl[2][4];
        #pragma unroll
        for (int mi = 0; mi < 4; mi++){
          int r = warp_m*64 + mi*16 + a_row_in;
          ldsm4(af[mi], &Ahi[r*AP + k16*16 + a_colb]);
        }
        #pragma unroll
        for (int nj = 0; nj < 2; nj++){
          int kr = k16*16 + b_krow;
          int nc = warp_n*32 + nj*16 + b_coln;
          ldsm4t(bh[nj], &Bhi[kr*BP + nc]);
          ldsm4t(bl[nj], &Blo[kr*BP + nc]);
        }
        #pragma unroll
        for (int mi = 0; mi < 4; mi++)
          #pragma unroll
          for (int ni = 0; ni < 4; ni++){
            const uint32_t* h = &bh[ni>>1][(ni&1)*2];
            const uint32_t* L = &bl[ni>>1][(ni&1)*2];
            mma_bf16(acc[mi][ni], af[mi], h[0], h[1]);
            mma_bf16(acc[mi][ni], af[mi], L[0], L[1]);
          }
        #pragma unroll
        for (int mi = 0; mi < 4; mi++){
          int r = warp_m*64 + mi*16 + a_row_in;
          ldsm4(af[mi], &Alo[r*AP + k16*16 + a_colb]);
        }
        #pragma unroll
        for (int mi = 0; mi < 4; mi++)
          #pragma unroll
          for (int ni = 0; ni < 4; ni++){
            const uint32_t* h = &bh[ni>>1][(ni&1)*2];
            mma_bf16(acc[mi][ni], af[mi], h[0], h[1]);
          }
      }
    }
  }

  #pragma unroll
  for (int mi = 0; mi < 4; mi++){
    int v0 = vbase + warp_m*64 + mi*16 + (lane >> 2);
    #pragma unroll
    for (int ni = 0; ni < 4; ni++){
      int col = warp_n*32 + ni*8 + (lane & 3)*2;
      float2 bb = *(const float2*)&bias[col];
      float2 r0, r1;
      r0.x = fmaxf(acc[mi][ni][0] + bb.x, 0.f);
      r0.y = fmaxf(acc[mi][ni][1] + bb.y, 0.f);
      r1.x = fmaxf(acc[mi][ni][2] + bb.x, 0.f);
      r1.y = fmaxf(acc[mi][ni][3] + bb.y, 0.f);
      *(float2*)&out[(size_t)v0*128 + col]     = r0;
      *(float2*)&out[(size_t)(v0+8)*128 + col] = r1;
    }
  }
}

// ---------------------------------------------------------------------------
// NEW (round 10): L3 on HMMA. Stride-2 deconv, in 16^3 x 128 -> out 32^3 x 128,
// parity decomposition (blockIdx.z). mma core copied from R9-proven mma_s1r;
// tap lists + scatter epilogue per R1-proven logic. No relu.
// ---------------------------------------------------------------------------
__global__ __launch_bounds__(256, 2) void mma_s2(
    const __nv_bfloat16* __restrict__ xhi, const __nv_bfloat16* __restrict__ xlo,
    const __nv_bfloat16* __restrict__ whi, const __nv_bfloat16* __restrict__ wlo,
    const float* __restrict__ bias, float* __restrict__ out)
{
  constexpr int BM = 128, BK = 32;
  constexpr int AP = 40;
  constexpr int BP = 136;

  __shared__ __align__(16) unsigned short Ahi[BM*AP];
  __shared__ __align__(16) unsigned short Alo[BM*AP];
  __shared__ __align__(16) unsigned short Bhi[BK*BP];
  __shared__ __align__(16) unsigned short Blo[BK*BP];
  __shared__ int offs[BM];

  const int tid  = threadIdx.x;
  const int lane = tid & 31;
  const int wid  = tid >> 5;
  const int warp_m = wid >> 2;
  const int warp_n = wid & 3;
  const int vbase = blockIdx.x * BM;
  const int pz = blockIdx.z;
  const int pd = (pz >> 2) & 1, ph = (pz >> 1) & 1, pw = pz & 1;

  // reduced-grid (16^3) coords for this thread's offs entry
  int md, mh, mw;
  { int rv = vbase + (tid & 127);
    mw = rv & 15; int t = rv >> 4; mh = t & 15; md = t >> 4; }

  // stride-2 tap lists (R1-proven mk logic)
  int nkd, kdL[2], ddL[2];
  int nkh, khL[2], dhL[2];
  int nkw, kwL[2], dwL[2];
  auto mk2 = [&](int p, int& n, int* kL, int* dL){
    if (p == 0){ n = 2; kL[0]=0; kL[1]=2; dL[0]=-1; dL[1]=0; }
    else       { n = 1; kL[0]=1; dL[0]=0; }
  };
  mk2(pd, nkd, kdL, ddL);
  mk2(ph, nkh, khL, dhL);
  mk2(pw, nkw, kwL, dwL);

  const int a_row_in = lane & 15;
  const int a_colb   = (lane >> 4) << 3;
  const int b_krow   = lane & 15;
  const int b_coln   = (lane >> 4) << 3;

  float acc[4][4][4];
  #pragma unroll
  for (int mi = 0; mi < 4; mi++)
    #pragma unroll
    for (int ni = 0; ni < 4; ni++)
      #pragma unroll
      for (int q = 0; q < 4; q++) acc[mi][ni][q] = 0.f;

  for (int ia = 0; ia < nkd; ia++)
  for (int ib = 0; ib < nkh; ib++)
  for (int ic = 0; ic < nkw; ic++){
    const int tap = (kdL[ia]*3 + khL[ib])*3 + kwL[ic];
    __syncthreads();
    if (tid < BM){
      int id = md + ddL[ia], ih = mh + dhL[ib], iw = mw + dwL[ic];
      bool v = (unsigned)id < 16u && (unsigned)ih < 16u && (unsigned)iw < 16u;
      offs[tid] = v ? ((id*16 + ih)*16 + iw) * 128 : -1;
    }

    for (int c0 = 0; c0 < 128; c0 += BK){
      __syncthreads();
      // A fill (gather, hi+lo)
      #pragma unroll
      for (int rep = 0; rep < 2; rep++){
        int idx = rep * 256 + tid;
        int row = idx >> 2, cg = idx & 3;
        int o = offs[row];
        uint4 h = make_uint4(0,0,0,0), l = make_uint4(0,0,0,0);
        if (o >= 0){
          h = *(const uint4*)(xhi + o + c0 + cg*8);
          l = *(const uint4*)(xlo + o + c0 + cg*8);
        }
        *(uint4*)&Ahi[row*AP + cg*8] = h;
        *(uint4*)&Alo[row*AP + cg*8] = l;
      }
      // B fill
      #pragma unroll
      for (int rep = 0; rep < 2; rep++){
        int idx = rep * 256 + tid;
        int kr = idx >> 4, cg = idx & 15;
        int src = tap*16384 + (c0 + kr)*128 + cg*8;
        *(uint4*)&Bhi[kr*BP + cg*8] = *(const uint4*)(whi + src);
        *(uint4*)&Blo[kr*BP + cg*8] = *(const uint4*)(wlo + src);
      }
      __syncthreads();

      #pragma unroll
      for (int k16 = 0; k16 < 2; k16++){
        uint32_t af[4][4], bh[2][4], bl[2][4];
        #pragma unroll
        for (int mi = 0; mi < 4; mi++){
          int r = warp_m*64 + mi*16 + a_row_in;
          ldsm4(af[mi], &Ahi[r*AP + k16*16 + a_colb]);
        }
        #pragma unroll
        for (int nj = 0; nj < 2; nj++){
          int kr = k16*16 + b_krow;
          int nc = warp_n*32 + nj*16 + b_coln;
          ldsm4t(bh[nj], &Bhi[kr*BP + nc]);
          ldsm4t(bl[nj], &Blo[kr*BP + nc]);
        }
        #pragma unroll
        for (int mi = 0; mi < 4; mi++)
          #pragma unroll
          for (int ni = 0; ni < 4; ni++){
            const uint32_t* h = &bh[ni>>1][(ni&1)*2];
            const uint32_t* L = &bl[ni>>1][(ni&1)*2];
            mma_bf16(acc[mi][ni], af[mi], h[0], h[1]);
            mma_bf16(acc[mi][ni], af[mi], L[0], L[1]);
          }
        #pragma unroll
        for (int mi = 0; mi < 4; mi++){
          int r = warp_m*64 + mi*16 + a_row_in;
          ldsm4(af[mi], &Alo[r*AP + k16*16 + a_colb]);
        }
        #pragma unroll
        for (int mi = 0; mi < 4; mi++)
          #pragma unroll
          for (int ni = 0; ni < 4; ni++){
            const uint32_t* h = &bh[ni>>1][(ni&1)*2];
            mma_bf16(acc[mi][ni], af[mi], h[0], h[1]);
          }
      }
    }
  }

  // epilogue: bias, scatter to strided output (R1-proven decomposition)
  #pragma unroll
  for (int mi = 0; mi < 4; mi++){
    int lv0 = warp_m*64 + mi*16 + (lane >> 2);
    #pragma unroll
    for (int ni = 0; ni < 4; ni++){
      int col = warp_n*32 + ni*8 + (lane & 3)*2;
      float2 bb = *(const float2*)&bias[col];
      #pragma unroll
      for (int h = 0; h < 2; h++){
        int rv = vbase + lv0 + h*8;
        int vw = rv & 15; int t = rv >> 4; int vh = t & 15; int vd = t >> 4;
        int od = 2*vd + pd, oh = 2*vh + ph, ow = 2*vw + pw;
        size_t oo = (size_t)((od*32 + oh)*32 + ow) * 128 + col;
        float2 r;
        r.x = acc[mi][ni][2*h+0] + bb.x;
        r.y = acc[mi][ni][2*h+1] + bb.y;
        *(float2*)&out[oo] = r;
      }
    }
  }
}

// ---------------------------------------------------------------------------
// Fused L5+L6 path tables (R6-proven).
// ---------------------------------------------------------------------------
__device__ __constant__ int c_np[2][3]   = {{2,2,0},{1,3,1}};
__device__ __constant__ int c_k1[2][3][3] = {{{1,0,0},{2,1,0},{0,0,0}},
                                             {{0,0,0},{2,1,0},{2,0,0}}};
__device__ __constant__ int c_k2[2][3][3] = {{{0,1,0},{1,2,0},{0,0,0}},
                                             {{0,0,0},{0,1,2},{2,0,0}}};

// P1 (R6-proven math; now also writes WpT directly, replacing p1t kernel)
__global__ __launch_bounds__(256) void p1_wp(
    const float* __restrict__ w2, const float* __restrict__ w20)
{
  int t = blockIdx.x * 256 + threadIdx.x;
  if (t >= 27*27*128) return;
  int ci = t & 127;
  int k2l = (t >> 7) % 27;
  int k1l = t / (27*128);
  const float* a = w2 + ((size_t)k1l*128 + ci) * 64;
  const float* b = w20 + (size_t)k2l * 64 * 3;
  float s0 = 0.f, s1 = 0.f, s2 = 0.f;
  #pragma unroll 4
  for (int cm = 0; cm < 64; cm++){
    float av = a[cm];
    s0 = fmaf(av, b[cm*3+0], s0);
    s1 = fmaf(av, b[cm*3+1], s1);
    s2 = fmaf(av, b[cm*3+2], s2);
  }
  float* o = g_Wp + (size_t)t * 3;
  o[0] = s0; o[1] = s1; o[2] = s2;
  size_t kk = (size_t)k1l*27 + k2l;
  g_WpT[kk*384 + 0*128 + ci] = s0;
  g_WpT[kk*384 + 1*128 + ci] = s1;
  g_WpT[kk*384 + 2*128 + ci] = s2;
}

// P2 (R7-proven, verbatim): Weff[pz][dxl][co][ci]
__global__ __launch_bounds__(256) void p2_weff()
{
  int t = blockIdx.x * 256 + threadIdx.x;
  if (t >= 8*27*128) return;
  int ci = t & 127;
  int dxl = (t >> 7) % 27;
  int pz = t / (27*128);
  int jd = dxl / 9, jh = (dxl / 3) % 3, jw = dxl % 3;
  int pd = (pz >> 2) & 1, ph = (pz >> 1) & 1, pw = pz & 1;
  int nd = c_np[pd][jd], nh = c_np[ph][jh], nw = c_np[pw][jw];
  float s0 = 0.f, s1 = 0.f, s2 = 0.f;
  for (int a = 0; a < nd; a++)
  for (int b = 0; b < nh; b++)
  for (int c = 0; c < nw; c++){
    int k1l = (c_k1[pd][jd][a]*3 + c_k1[ph][jh][b])*3 + c_k1[pw][jw][c];
    int k2l = (c_k2[pd][jd][a]*3 + c_k2[ph][jh][b])*3 + c_k2[pw][jw][c];
    const float* wp = g_Wp + ((size_t)(k1l*27 + k2l)*128 + ci)*3;
    s0 += wp[0]; s1 += wp[1]; s2 += wp[2];
  }
  float* o = g_Weff + (size_t)(pz*27 + dxl) * 3 * 128;
  o[0*128 + ci] = s0;
  o[1*128 + ci] = s1;
  o[2*128 + ci] = s2;
}

// P3 (R6-proven, verbatim)
__global__ void p3_bias(const float* __restrict__ w20,
                        const float* __restrict__ b2,
                        const float* __restrict__ b20)
{
  int tid = threadIdx.x;
  if (tid < 81){
    int k2 = tid / 3, co = tid % 3;
    float s = 0.f;
    for (int cm = 0; cm < 64; cm++)
      s = fmaf(w20[(k2*64+cm)*3+co], b2[cm], s);
    g_bconv[tid] = s;
  }
  __syncthreads();
  if (tid < 3){
    float s = b20[tid];
    for (int k2 = 0; k2 < 27; k2++) s += g_bconv[k2*3+tid];
    g_btot[tid] = s;
  }
}

// ---------------------------------------------------------------------------
// Fused L5+L6 consumer (R7-proven, verbatim).
// ---------------------------------------------------------------------------
__global__ __launch_bounds__(256) void fused56b(
    const float* __restrict__ x, float* __restrict__ out)
{
  const int wid  = threadIdx.x >> 5;
  const int lane = threadIdx.x & 31;
  const int pz = blockIdx.z;
  const int pd = (pz >> 2) & 1, ph = (pz >> 1) & 1, pw = pz & 1;
  const int wg  = blockIdx.x * 8 + wid;
  const int seg = wg & 3;
  const int row = wg >> 2;
  const int rd = row >> 5, rh = row & 31;
  const int rw0 = seg * 8;
  const int l2 = 2 * lane;

  ull acc[8][3];
  #pragma unroll
  for (int r = 0; r < 8; r++)
    #pragma unroll
    for (int c = 0; c < 3; c++) acc[r][c] = 0ull;

  for (int jd = 0; jd <= 1 + pd; jd++){
    int id = rd + jd - 1;
    if ((unsigned)id >= 32u) continue;
    for (int jh = 0; jh <= 1 + ph; jh++){
      int ih = rh + jh - 1;
      if ((unsigned)ih >= 32u) continue;
      const float* xrow = x + (size_t)((id*32 + ih)*32) * 128;
      for (int jw = 0; jw <= 1 + pw; jw++){
        const int dxl = jd*9 + jh*3 + jw;
        const float* Wt = g_Weff + (size_t)(pz*27 + dxl) * 3 * 128;
        ull w00 = *(const ull*)(Wt +   0 + l2);
        ull w01 = *(const ull*)(Wt +  64 + l2);
        ull w10 = *(const ull*)(Wt + 128 + l2);
        ull w11 = *(const ull*)(Wt + 192 + l2);
        ull w20 = *(const ull*)(Wt + 256 + l2);
        ull w21 = *(const ull*)(Wt + 320 + l2);
        #pragma unroll
        for (int r = 0; r < 8; r++){
          int iw = rw0 + r + jw - 1;
          if ((unsigned)iw < 32u){
            const float* xp = xrow + iw * 128;
            ull x0 = *(const ull*)(xp + l2);
            ull x1 = *(const ull*)(xp + 64 + l2);
            ffma2(acc[r][0], x0, w00); ffma2(acc[r][0], x1, w01);
            ffma2(acc[r][1], x0, w10); ffma2(acc[r][1], x1, w11);
            ffma2(acc[r][2], x0, w20); ffma2(acc[r][2], x1, w21);
          }
        }
      }
    }
  }

  const float bt0 = g_btot[0], bt1 = g_btot[1], bt2 = g_btot[2];
  const int od = 2*rd + pd, oh = 2*rh + ph;

  #pragma unroll
  for (int r = 0; r < 8; r++){
    float s0, s1, s2;
    {
      float a, b;
      unpack2(acc[r][0], a, b); s0 = a + b;
      unpack2(acc[r][1], a, b); s1 = a + b;
      unpack2(acc[r][2], a, b); s2 = a + b;
    }
    #pragma unroll
    for (int sh = 16; sh > 0; sh >>= 1){
      s0 += __shfl_xor_sync(0xffffffffu, s0, sh);
      s1 += __shfl_xor_sync(0xffffffffu, s1, sh);
      s2 += __shfl_xor_sync(0xffffffffu, s2, sh);
    }
    if (lane == 0){
      int ow = 2*(rw0 + r) + pw;
      float* op = out + (size_t)((od*64 + oh)*64 + ow) * 3;
      op[0] = s0 + bt0;
      op[1] = s1 + bt1;
      op[2] = s2 + bt2;
    }
  }
}

// ---------------------------------------------------------------------------
// fix56w (R8-proven, verbatim): warp-per-voxel exact boundary fix.
// ---------------------------------------------------------------------------
__global__ __launch_bounds__(256) void fix56w(
    const float* __restrict__ x, const float* __restrict__ b20,
    float* __restrict__ out)
{
  const int gw = blockIdx.x * 8 + (threadIdx.x >> 5);
  const int lane = threadIdx.x & 31;
  const int l2 = 2 * lane;

  int plane = gw / 4096, r = gw % 4096;
  int a = r / 64, b = r % 64;
  int od, oh, ow;
  if      (plane == 0){ od = 0;  oh = a; ow = b; }
  else if (plane == 1){ od = 63; oh = a; ow = b; }
  else if (plane == 2){ oh = 0;  od = a; ow = b; if (od==0||od==63) return; }
  else if (plane == 3){ oh = 63; od = a; ow = b; if (od==0||od==63) return; }
  else if (plane == 4){ ow = 0;  od = a; oh = b; if (od==0||od==63||oh==0||oh==63) return; }
  else               { ow = 63; od = a; oh = b; if (od==0||od==63||oh==0||oh==63) return; }

  ull a0 = 0ull, a1 = 0ull, a2 = 0ull;
  float bias0 = __ldg(&b20[0]), bias1 = __ldg(&b20[1]), bias2 = __ldg(&b20[2]);

  for (int k2d = 0; k2d < 3; k2d++){
    int md = od + k2d - 1; if ((unsigned)md >= 64u) continue;
    int pmd = md & 1, rd = (md - pmd) >> 1;
    int n_d = pmd ? 1 : 2;
    int k1d[2], ixd[2];
    if (pmd){ k1d[0] = 1; ixd[0] = rd; }
    else    { k1d[0] = 0; ixd[0] = rd - 1; k1d[1] = 2; ixd[1] = rd; }
    for (int k2h = 0; k2h < 3; k2h++){
      int mh = oh + k2h - 1; if ((unsigned)mh >= 64u) continue;
      int pmh = mh & 1, rh = (mh - pmh) >> 1;
      int n_h = pmh ? 1 : 2;
      int k1h[2], ixh[2];
      if (pmh){ k1h[0] = 1; ixh[0] = rh; }
      else    { k1h[0] = 0; ixh[0] = rh - 1; k1h[1] = 2; ixh[1] = rh; }
      for (int k2w = 0; k2w < 3; k2w++){
        int mw = ow + k2w - 1; if ((unsigned)mw >= 64u) continue;
        int pmw = mw & 1, rw = (mw - pmw) >> 1;
        int n_w = pmw ? 1 : 2;
        int k1w[2], ixw[2];
        if (pmw){ k1w[0] = 1; ixw[0] = rw; }
        else    { k1w[0] = 0; ixw[0] = rw - 1; k1w[1] = 2; ixw[1] = rw; }

        int k2l = (k2d*3 + k2h)*3 + k2w;
        bias0 += g_bconv[k2l*3+0];
        bias1 += g_bconv[k2l*3+1];
        bias2 += g_bconv[k2l*3+2];

        for (int ia = 0; ia < n_d; ia++){
          if ((unsigned)ixd[ia] >= 32u) continue;
          for (int ib = 0; ib < n_h; ib++){
            if ((unsigned)ixh[ib] >= 32u) continue;
            for (int ic = 0; ic < n_w; ic++){
              if ((unsigned)ixw[ic] >= 32u) continue;
              int k1l = (k1d[ia]*3 + k1h[ib])*3 + k1w[ic];
              const float* wt = g_WpT + (size_t)(k1l*27 + k2l)*384;
              const float* xp = x + (size_t)((ixd[ia]*32 + ixh[ib])*32 + ixw[ic])*128;
              ull x0 = *(const ull*)(xp + l2);
              ull x1 = *(const ull*)(xp + 64 + l2);
              ffma2(a0, x0, *(const ull*)(wt +   0 + l2));
              ffma2(a0, x1, *(const ull*)(wt +  64 + l2));
              ffma2(a1, x0, *(const ull*)(wt + 128 + l2));
              ffma2(a1, x1, *(const ull*)(wt + 192 + l2));
              ffma2(a2, x0, *(const ull*)(wt + 256 + l2));
              ffma2(a2, x1, *(const ull*)(wt + 320 + l2));
            }
          }
        }
      }
    }
  }

  float s0, s1, s2;
  {
    float u, v;
    unpack2(a0, u, v); s0 = u + v;
    unpack2(a1, u, v); s1 = u + v;
    unpack2(a2, u, v); s2 = u + v;
  }
  #pragma unroll
  for (int sh = 16; sh > 0; sh >>= 1){
    s0 += __shfl_xor_sync(0xffffffffu, s0, sh);
    s1 += __shfl_xor_sync(0xffffffffu, s1, sh);
    s2 += __shfl_xor_sync(0xffffffffu, s2, sh);
  }
  if (lane == 0){
    float* op = out + (size_t)((od*64 + oh)*64 + ow) * 3;
    op[0] = s0 + bias0;
    op[1] = s1 + bias1;
    op[2] = s2 + bias2;
  }
}

// ---------------------------------------------------------------------------
// kernel_launch — ordered so launch #6 (the ncu-profiled one) is mma_s2.
// ---------------------------------------------------------------------------
extern "C" void kernel_launch(void* const* d_in, const int* in_sizes, int n_in,
                              void* d_out, int out_size)
{
  (void)in_sizes; (void)n_in; (void)out_size;
  const float* x   = (const float*)d_in[0];
  const float* w0  = (const float*)d_in[1];
  const float* b0  = (const float*)d_in[2];
  const float* w00 = (const float*)d_in[3];
  const float* b00 = (const float*)d_in[4];
  const float* w1  = (const float*)d_in[5];
  const float* b1  = (const float*)d_in[6];
  const float* w10 = (const float*)d_in[7];
  const float* b10 = (const float*)d_in[8];
  const float* w2  = (const float*)d_in[9];
  const float* b2  = (const float*)d_in[10];
  const float* w20 = (const float*)d_in[11];
  const float* b20 = (const float*)d_in[12];
  float* out = (float*)d_out;

  float *bufA = nullptr, *bufB = nullptr;
  __nv_bfloat16 *xhi, *xlo, *whi, *wlo, *whiB, *wloB;
  cudaGetSymbolAddress((void**)&bufA, g_bufA);
  cudaGetSymbolAddress((void**)&bufB, g_bufB);
  cudaGetSymbolAddress((void**)&xhi, g_xhi);
  cudaGetSymbolAddress((void**)&xlo, g_xlo);
  cudaGetSymbolAddress((void**)&whi, g_whi);
  cudaGetSymbolAddress((void**)&wlo, g_wlo);
  cudaGetSymbolAddress((void**)&whiB, g_whiB);
  cudaGetSymbolAddress((void**)&wloB, g_wloB);

  // (1) Wp + WpT precompute (input-only deps)
  p1_wp<<<(27*27*128 + 255)/256, 256>>>(w2, w20);
  // (2) split w1 for L3 HMMA
  split_w_kernel<<<1728, 256>>>(w1, whiB, wloB);
  // (3) L1: deconv0 s2: x(8^3,128) -> bufA(16^3,128)   [R1 proven]
  {
    dim3 g(512/32, 128/64, 8);
    deconv_gemm<32,2><<<g, 256>>>(x,  w0,  b0,  bufA,
                                  8,8,8,128,  16,16,16,128, 2, 0);
  }
  // (4) L2: deconv0_0 s1 + relu: bufA -> bufB(16^3,128)   [R1 proven]
  {
    dim3 g(4096/32, 128/64, 1);
    deconv_gemm<32,2><<<g, 256>>>(bufA, w00, b00, bufB,
                                  16,16,16,128, 16,16,16,128, 1, 1);
  }
  // (5) split L2 output for L3 HMMA
  split_x_kernel<<<512, 256>>>(bufB, xhi, xlo, 524288/4);
  // (6) L3 on HMMA: bufB-split -> bufA(32^3,128)   [NEW — profiled launch]
  {
    dim3 g(32, 1, 8);
    mma_s2<<<g, 256>>>(xhi, xlo, whiB, wloB, b1, bufA);
  }
  // (7) split w10 for L4 HMMA
  split_w_kernel<<<1728, 256>>>(w10, whi, wlo);
  // (8) split L3 output for L4 HMMA
  split_x_kernel<<<4096, 256>>>(bufA, xhi, xlo, 4194304/4);
  // (9) L4 on HMMA   [R9 proven]
  mma_s1r<<<256, 256>>>(xhi, xlo, whi, wlo, b10, bufB);
  // (10-11) fused-weight precompute for L5+L6
  p2_weff<<<(8*27*128 + 255)/256, 256>>>();
  p3_bias<<<1, 128>>>(w20, b2, b20);
  // (12) Fused L5+L6   [R7 proven]
  {
    dim3 g(512, 1, 8);
    fused56b<<<g, 256>>>(bufB, out);
  }
  // (13) Exact boundary fix   [R8 proven]
  fix56w<<<3072, 256>>>(bufB, b20, out);
}